// round 1
// baseline (speedup 1.0000x reference)
#include <cuda_runtime.h>
#include <math.h>

#define NN 100000
#define CC 128
#define EE 1600000
#define HH 4
#define DD 32
#define LL 2

// ---------------- device scratch (allocation-free: static globals) ----------
__device__ int   g_is64;
__device__ int   g_src[EE];
__device__ int   g_dst[EE];
__device__ int   g_srcs[EE];          // src indices sorted by dst
__device__ int   g_count[NN];
__device__ int   g_rowstart[NN + 2];
__device__ int   g_cursor[NN];
__device__ int   g_bsum[128];
__device__ int   g_bsum2[128];
__device__ float g_qkv[(size_t)NN * 384];   // [n][0:128]=Q  [128:256]=K'  [256:384]=V'
__device__ float g_ez[(size_t)EE * 4];      // unnormalized exp per sorted edge x head
__device__ float g_agg[(size_t)NN * CC];
__device__ float g_h[(size_t)NN * CC];
__device__ float g_W3[CC * 384];            // folded [Wq | Wk@a_rel | Wv@m_rel]
__device__ float g_b3[384];

// ---------------- edge-index dtype detection + conversion -------------------
__global__ void k_detect(const void* ei) {
    const long long* q = (const long long*)ei;
    int is64 = 1;
    for (int i = 0; i < 64; i++) {
        long long v = q[i];
        if (v < 0 || v >= NN) { is64 = 0; break; }
    }
    g_is64 = is64;
}

__global__ void k_convert(const void* ei, int E) {
    int e = blockIdx.x * blockDim.x + threadIdx.x;
    if (e >= E) return;
    if (g_is64) {
        const long long* p = (const long long*)ei;
        g_src[e] = (int)p[e];
        g_dst[e] = (int)p[(size_t)E + e];
    } else {
        const int* p = (const int*)ei;
        g_src[e] = p[e];
        g_dst[e] = p[(size_t)E + e];
    }
}

// ---------------- counting sort by dst ---------------------------------------
__global__ void k_zero(int n) {
    int i = blockIdx.x * blockDim.x + threadIdx.x;
    if (i < n) g_count[i] = 0;
}

__global__ void k_hist(int E) {
    int e = blockIdx.x * blockDim.x + threadIdx.x;
    if (e < E) atomicAdd(&g_count[g_dst[e]], 1);
}

__global__ void k_scan1(int n) {
    __shared__ int sh[1024];
    int i = blockIdx.x * 1024 + threadIdx.x;
    int v = (i < n) ? g_count[i] : 0;
    sh[threadIdx.x] = v;
    __syncthreads();
    for (int off = 1; off < 1024; off <<= 1) {
        int t = (threadIdx.x >= off) ? sh[threadIdx.x - off] : 0;
        __syncthreads();
        sh[threadIdx.x] += t;
        __syncthreads();
    }
    if (i < n) g_rowstart[i] = sh[threadIdx.x] - v;  // exclusive
    if (threadIdx.x == 1023) g_bsum[blockIdx.x] = sh[1023];
}

__global__ void k_scan2(int nb) {
    __shared__ int sh[128];
    int v = (threadIdx.x < nb) ? g_bsum[threadIdx.x] : 0;
    sh[threadIdx.x] = v;
    __syncthreads();
    for (int off = 1; off < 128; off <<= 1) {
        int t = (threadIdx.x >= off) ? sh[threadIdx.x - off] : 0;
        __syncthreads();
        sh[threadIdx.x] += t;
        __syncthreads();
    }
    g_bsum2[threadIdx.x] = sh[threadIdx.x] - v;      // exclusive
}

__global__ void k_scan3(int n, int E) {
    int i = blockIdx.x * blockDim.x + threadIdx.x;
    if (i < n) {
        int r = g_rowstart[i] + g_bsum2[i >> 10];
        g_rowstart[i] = r;
        g_cursor[i] = r;
    }
    if (i == 0) g_rowstart[n] = E;
}

__global__ void k_scatter(int E) {
    int e = blockIdx.x * blockDim.x + threadIdx.x;
    if (e >= E) return;
    int d = g_dst[e];
    int pos = atomicAdd(&g_cursor[d], 1);
    g_srcs[pos] = g_src[e];
}

// ---------------- fold relation transforms into weights ----------------------
__global__ void k_fold(const float* __restrict__ Wq, const float* __restrict__ Wk,
                       const float* __restrict__ Wv, const float* __restrict__ bq,
                       const float* __restrict__ bk, const float* __restrict__ bv,
                       const float* __restrict__ a_rel, const float* __restrict__ m_rel,
                       int l) {
    int idx = blockIdx.x * blockDim.x + threadIdx.x;
    if (idx >= CC * 384) return;
    int c = idx / 384, j = idx % 384;
    float val;
    if (j < 128) {
        val = Wq[((size_t)l * CC + c) * CC + j];
    } else {
        int e = (j < 256) ? j - 128 : j - 256;
        int h = e >> 5, ee = e & 31;
        const float* Wx = (j < 256) ? Wk : Wv;
        const float* Rx = (j < 256) ? a_rel : m_rel;
        const float* wrow = Wx + ((size_t)l * CC + c) * CC + h * DD;
        const float* rr = Rx + ((size_t)(l * HH + h) * DD) * DD + ee;
        float s = 0.f;
#pragma unroll
        for (int d = 0; d < DD; d++) s += wrow[d] * rr[d * DD];
        val = s;
    }
    g_W3[c * 384 + j] = val;
    if (c == 0) {
        float bval;
        if (j < 128) {
            bval = bq[l * CC + j];
        } else {
            int e = (j < 256) ? j - 128 : j - 256;
            int h = e >> 5, ee = e & 31;
            const float* bx = (j < 256) ? bk : bv;
            const float* Rx = (j < 256) ? a_rel : m_rel;
            float s = 0.f;
#pragma unroll
            for (int d = 0; d < DD; d++)
                s += bx[l * CC + h * DD + d] * Rx[((size_t)(l * HH + h) * DD + d) * DD + ee];
            bval = s;
        }
        g_b3[j] = bval;
    }
}

// ---------------- fp32 tiled GEMM: C[M x Ncols] = A[M x 128] @ B[128 x Ncols] -
// BM=BN=64, BK=16, 256 threads, 4x4 microtile per thread.
template <bool GELU, bool SKIPB>
__global__ void __launch_bounds__(256) k_gemm(
    const float* __restrict__ A, int lda,
    const float* __restrict__ B, int ldb,
    const float* __restrict__ bias,
    float* __restrict__ C, int ldc, int M,
    const float* __restrict__ hold, int ldh,
    const float* __restrict__ skipp) {
    __shared__ float As[16][68];
    __shared__ float Bs[16][64];
    const int t = threadIdx.x;
    const int m0 = blockIdx.y * 64, n0 = blockIdx.x * 64;
    const int tr = t >> 4, tc = t & 15;
    const int a_k = t & 15, a_m = t >> 4;
    const int b_n = t & 63, b_k = t >> 6;
    float acc[4][4];
#pragma unroll
    for (int i = 0; i < 4; i++)
#pragma unroll
        for (int j = 0; j < 4; j++) acc[i][j] = 0.f;

    for (int k0 = 0; k0 < CC; k0 += 16) {
#pragma unroll
        for (int i = 0; i < 4; i++) {
            int m = a_m + i * 16;
            int gm = m0 + m;
            float v = (gm < M) ? A[(size_t)gm * lda + k0 + a_k] : 0.f;
            if (GELU) v = v * normcdff(v);
            As[a_k][m] = v;
        }
#pragma unroll
        for (int i = 0; i < 4; i++) {
            int k = b_k + i * 4;
            Bs[k][b_n] = B[(size_t)(k0 + k) * ldb + n0 + b_n];
        }
        __syncthreads();
#pragma unroll
        for (int kk = 0; kk < 16; kk++) {
            float4 av = *(const float4*)&As[kk][tr * 4];
            float4 bv = *(const float4*)&Bs[kk][tc * 4];
            acc[0][0] += av.x * bv.x; acc[0][1] += av.x * bv.y;
            acc[0][2] += av.x * bv.z; acc[0][3] += av.x * bv.w;
            acc[1][0] += av.y * bv.x; acc[1][1] += av.y * bv.y;
            acc[1][2] += av.y * bv.z; acc[1][3] += av.y * bv.w;
            acc[2][0] += av.z * bv.x; acc[2][1] += av.z * bv.y;
            acc[2][2] += av.z * bv.z; acc[2][3] += av.z * bv.w;
            acc[3][0] += av.w * bv.x; acc[3][1] += av.w * bv.y;
            acc[3][2] += av.w * bv.z; acc[3][3] += av.w * bv.w;
        }
        __syncthreads();
    }

    float4 bb = *(const float4*)&bias[n0 + tc * 4];
    float g = 0.f, og = 0.f;
    if (SKIPB) {
        g = 1.f / (1.f + expf(-skipp[0]));
        og = 1.f - g;
    }
#pragma unroll
    for (int i = 0; i < 4; i++) {
        int gm = m0 + tr * 4 + i;
        if (gm < M) {
            float4 c;
            c.x = acc[i][0] + bb.x;
            c.y = acc[i][1] + bb.y;
            c.z = acc[i][2] + bb.z;
            c.w = acc[i][3] + bb.w;
            if (SKIPB) {
                float4 hv = *(const float4*)&hold[(size_t)gm * ldh + n0 + tc * 4];
                c.x = g * c.x + og * hv.x;
                c.y = g * c.y + og * hv.y;
                c.z = g * c.z + og * hv.z;
                c.w = g * c.w + og * hv.w;
            }
            *(float4*)&C[(size_t)gm * ldc + n0 + tc * 4] = c;
        }
    }
}

// ---------------- edge phase: one warp per dst node ---------------------------
// lane layout: head = lane/8, each lane holds 4 consecutive channels (float4).
__global__ void __launch_bounds__(256) k_edge(const float* __restrict__ prel) {
    int w = (blockIdx.x * blockDim.x + threadIdx.x) >> 5;
    int lane = threadIdx.x & 31;
    if (w >= NN) return;
    int r0 = g_rowstart[w], r1 = g_rowstart[w + 1];
    int h = lane >> 3;
    const float4 q4 = *(const float4*)&g_qkv[(size_t)w * 384 + lane * 4];
    const float scale = prel[h] * 0.17677669529663687f;  // 1/sqrt(32)
    float denom = 0.f;
    for (int j = r0; j < r1; j++) {
        int s = g_srcs[j];
        const float4 k4 = *(const float4*)&g_qkv[(size_t)s * 384 + 128 + lane * 4];
        float p = q4.x * k4.x + q4.y * k4.y + q4.z * k4.z + q4.w * k4.w;
        p += __shfl_xor_sync(0xffffffffu, p, 1);
        p += __shfl_xor_sync(0xffffffffu, p, 2);
        p += __shfl_xor_sync(0xffffffffu, p, 4);
        float ev = __expf(p * scale);
        denom += ev;
        if ((lane & 7) == 0) g_ez[(size_t)j * 4 + h] = ev;
    }
    float inv = (r1 > r0) ? 1.f / denom : 0.f;
    float4 acc = {0.f, 0.f, 0.f, 0.f};
    for (int j = r0; j < r1; j++) {
        int s = g_srcs[j];
        const float4 v4 = *(const float4*)&g_qkv[(size_t)s * 384 + 256 + lane * 4];
        float wt = g_ez[(size_t)j * 4 + h] * inv;
        acc.x += v4.x * wt;
        acc.y += v4.y * wt;
        acc.z += v4.z * wt;
        acc.w += v4.w * wt;
    }
    *(float4*)&g_agg[(size_t)w * CC + lane * 4] = acc;
}

// ---------------- final FC: out[N x 2] = h @ Wfc + bfc ------------------------
__global__ void __launch_bounds__(256) k_fc(const float* __restrict__ h,
                                            const float* __restrict__ Wfc,
                                            const float* __restrict__ bfc,
                                            float* __restrict__ out) {
    int w = (blockIdx.x * blockDim.x + threadIdx.x) >> 5;
    int lane = threadIdx.x & 31;
    if (w >= NN) return;
    float4 hv = *(const float4*)&h[(size_t)w * CC + lane * 4];
    float4 wa = *(const float4*)&Wfc[lane * 8];      // {W[c][0],W[c][1],W[c+1][0],W[c+1][1]}
    float4 wb = *(const float4*)&Wfc[lane * 8 + 4];
    float d0 = hv.x * wa.x + hv.y * wa.z + hv.z * wb.x + hv.w * wb.z;
    float d1 = hv.x * wa.y + hv.y * wa.w + hv.z * wb.y + hv.w * wb.w;
#pragma unroll
    for (int off = 16; off > 0; off >>= 1) {
        d0 += __shfl_xor_sync(0xffffffffu, d0, off);
        d1 += __shfl_xor_sync(0xffffffffu, d1, off);
    }
    if (lane == 0) {
        out[(size_t)w * 2]     = d0 + bfc[0];
        out[(size_t)w * 2 + 1] = d1 + bfc[1];
    }
}

// -----------------------------------------------------------------------------
extern "C" void kernel_launch(void* const* d_in, const int* in_sizes, int n_in,
                              void* d_out, int out_size) {
    const float* x     = (const float*)d_in[0];
    const void*  ei    = d_in[1];
    const float* Wk    = (const float*)d_in[2];
    const float* bk    = (const float*)d_in[3];
    const float* Wq    = (const float*)d_in[4];
    const float* bq    = (const float*)d_in[5];
    const float* Wv    = (const float*)d_in[6];
    const float* bv    = (const float*)d_in[7];
    const float* a_rel = (const float*)d_in[8];
    const float* m_rel = (const float*)d_in[9];
    const float* p_rel = (const float*)d_in[10];
    const float* Wa    = (const float*)d_in[11];
    const float* ba    = (const float*)d_in[12];
    const float* skip  = (const float*)d_in[13];
    const float* Wfc   = (const float*)d_in[14];
    const float* bfc   = (const float*)d_in[15];
    float* out = (float*)d_out;

    int E = in_sizes[1] / 2;
    if (E > EE) E = EE;

    float *p_h, *p_agg, *p_qkv, *p_W3, *p_b3;
    cudaGetSymbolAddress((void**)&p_h, g_h);
    cudaGetSymbolAddress((void**)&p_agg, g_agg);
    cudaGetSymbolAddress((void**)&p_qkv, g_qkv);
    cudaGetSymbolAddress((void**)&p_W3, g_W3);
    cudaGetSymbolAddress((void**)&p_b3, g_b3);

    int eb = (E + 255) / 256;
    int nb1024 = (NN + 1023) / 1024;

    k_detect<<<1, 1>>>(ei);
    k_convert<<<eb, 256>>>(ei, E);
    k_zero<<<(NN + 255) / 256, 256>>>(NN);
    k_hist<<<eb, 256>>>(E);
    k_scan1<<<nb1024, 1024>>>(NN);
    k_scan2<<<1, 128>>>(nb1024);
    k_scan3<<<(NN + 255) / 256, 256>>>(NN, E);
    k_scatter<<<eb, 256>>>(E);

    for (int l = 0; l < LL; l++) {
        const float* A = (l == 0) ? x : p_h;
        k_fold<<<(CC * 384 + 255) / 256, 256>>>(Wq, Wk, Wv, bq, bk, bv, a_rel, m_rel, l);
        k_gemm<false, false><<<dim3(384 / 64, (NN + 63) / 64), 256>>>(
            A, CC, p_W3, 384, p_b3, p_qkv, 384, NN, nullptr, 0, nullptr);
        k_edge<<<(NN * 32 + 255) / 256, 256>>>(p_rel + (size_t)l * HH);
        k_gemm<true, true><<<dim3(CC / 64, (NN + 63) / 64), 256>>>(
            p_agg, CC, Wa + (size_t)l * CC * CC, CC, ba + (size_t)l * CC,
            p_h, CC, NN, A, CC, skip + l);
    }
    k_fc<<<(NN * 32 + 255) / 256, 256>>>(p_h, Wfc, bfc, out);
}

// round 4
// speedup vs baseline: 1.4866x; 1.4866x over previous
#include <cuda_runtime.h>
#include <cuda_bf16.h>
#include <math.h>
#include <stdint.h>

#define NN 100000
#define CC 128
#define EE 1600000
#define HH 4
#define DD 32
#define LL 2

// ---------------- device scratch (allocation-free: static globals) ----------
__device__ int   g_is64;
__device__ int   g_src[EE];
__device__ int   g_dst[EE];
__device__ int   g_srcs[EE];
__device__ int   g_count[NN];
__device__ int   g_rowstart[NN + 2];
__device__ int   g_cursor[NN];
__device__ int   g_bsum[128];
__device__ int   g_bsum2[128];
__device__ float g_qkv[(size_t)NN * 384];     // [n][0:128]=Q  [128:256]=K'  [256:384]=V'
__device__ float g_agg[(size_t)NN * CC];
__device__ float g_h[(size_t)NN * CC];
__device__ float g_W3[CC * 384];              // folded fp32 [Wq | Wk@a_rel | Wv@m_rel]
__device__ float g_b3[384];
__device__ __nv_bfloat16 g_abf[(size_t)NN * 256];   // A split: [row][0:128]=hi [128:256]=lo
__device__ __nv_bfloat16 g_w3bf[384 * 256];         // W3^T split: [n][0:128]=hi [128:256]=lo
__device__ __nv_bfloat16 g_wabf[128 * 256];         // Wa^T split

// ---------------- edge-index dtype detection + conversion -------------------
__global__ void k_detect(const void* ei) {
    const long long* q = (const long long*)ei;
    int is64 = 1;
    for (int i = 0; i < 64; i++) {
        long long v = q[i];
        if (v < 0 || v >= NN) { is64 = 0; break; }
    }
    g_is64 = is64;
}

__global__ void k_zero(int n) {
    int i = blockIdx.x * blockDim.x + threadIdx.x;
    if (i < n) g_count[i] = 0;
}

__global__ void k_convert(const void* ei, int E) {
    int e = blockIdx.x * blockDim.x + threadIdx.x;
    if (e >= E) return;
    int s, d;
    if (g_is64) {
        const long long* p = (const long long*)ei;
        s = (int)p[e];
        d = (int)p[(size_t)E + e];
    } else {
        const int* p = (const int*)ei;
        s = p[e];
        d = p[(size_t)E + e];
    }
    g_src[e] = s;
    g_dst[e] = d;
    atomicAdd(&g_count[d], 1);
}

// ---------------- counting sort by dst ---------------------------------------
__global__ void k_scan1(int n) {
    __shared__ int sh[1024];
    int i = blockIdx.x * 1024 + threadIdx.x;
    int v = (i < n) ? g_count[i] : 0;
    sh[threadIdx.x] = v;
    __syncthreads();
    for (int off = 1; off < 1024; off <<= 1) {
        int t = (threadIdx.x >= off) ? sh[threadIdx.x - off] : 0;
        __syncthreads();
        sh[threadIdx.x] += t;
        __syncthreads();
    }
    if (i < n) g_rowstart[i] = sh[threadIdx.x] - v;
    if (threadIdx.x == 1023) g_bsum[blockIdx.x] = sh[1023];
}

__global__ void k_scan2(int nb) {
    __shared__ int sh[128];
    int v = (threadIdx.x < nb) ? g_bsum[threadIdx.x] : 0;
    sh[threadIdx.x] = v;
    __syncthreads();
    for (int off = 1; off < 128; off <<= 1) {
        int t = (threadIdx.x >= off) ? sh[threadIdx.x - off] : 0;
        __syncthreads();
        sh[threadIdx.x] += t;
        __syncthreads();
    }
    g_bsum2[threadIdx.x] = sh[threadIdx.x] - v;
}

__global__ void k_scan3(int n, int E) {
    int i = blockIdx.x * blockDim.x + threadIdx.x;
    if (i < n) {
        int r = g_rowstart[i] + g_bsum2[i >> 10];
        g_rowstart[i] = r;
        g_cursor[i] = r;
    }
    if (i == 0) g_rowstart[n] = E;
}

__global__ void k_scatter(int E) {
    int e = blockIdx.x * blockDim.x + threadIdx.x;
    if (e >= E) return;
    int d = g_dst[e];
    int pos = atomicAdd(&g_cursor[d], 1);
    g_srcs[pos] = g_src[e];
}

// ---------------- fold relation transforms into fp32 weights ------------------
__global__ void k_fold(const float* __restrict__ Wq, const float* __restrict__ Wk,
                       const float* __restrict__ Wv, const float* __restrict__ bq,
                       const float* __restrict__ bk, const float* __restrict__ bv,
                       const float* __restrict__ a_rel, const float* __restrict__ m_rel,
                       int l) {
    int idx = blockIdx.x * blockDim.x + threadIdx.x;
    if (idx >= CC * 384) return;
    int c = idx / 384, j = idx % 384;
    float val;
    if (j < 128) {
        val = Wq[((size_t)l * CC + c) * CC + j];
    } else {
        int e = (j < 256) ? j - 128 : j - 256;
        int h = e >> 5, ee = e & 31;
        const float* Wx = (j < 256) ? Wk : Wv;
        const float* Rx = (j < 256) ? a_rel : m_rel;
        const float* wrow = Wx + ((size_t)l * CC + c) * CC + h * DD;
        const float* rr = Rx + ((size_t)(l * HH + h) * DD) * DD + ee;
        float s = 0.f;
#pragma unroll
        for (int d = 0; d < DD; d++) s += wrow[d] * rr[d * DD];
        val = s;
    }
    g_W3[c * 384 + j] = val;
    if (c == 0) {
        float bval;
        if (j < 128) {
            bval = bq[l * CC + j];
        } else {
            int e = (j < 256) ? j - 128 : j - 256;
            int h = e >> 5, ee = e & 31;
            const float* bx = (j < 256) ? bk : bv;
            const float* Rx = (j < 256) ? a_rel : m_rel;
            float s = 0.f;
#pragma unroll
            for (int d = 0; d < DD; d++)
                s += bx[l * CC + h * DD + d] * Rx[((size_t)(l * HH + h) * DD + d) * DD + ee];
            bval = s;
        }
        g_b3[j] = bval;
    }
}

// ---------------- transpose + hi/lo bf16 split of weights --------------------
// W is [128 x Ncols] row-major (K x N); dst is [Ncols x 256] with hi cols 0:128, lo 128:256
__global__ void k_wsplit(const float* __restrict__ W, __nv_bfloat16* __restrict__ dst,
                         int Ncols) {
    int idx = blockIdx.x * blockDim.x + threadIdx.x;
    if (idx >= 128 * Ncols) return;
    int n = idx >> 7, k = idx & 127;
    float v = W[(size_t)k * Ncols + n];
    __nv_bfloat16 hi = __float2bfloat16_rn(v);
    __nv_bfloat16 lo = __float2bfloat16_rn(v - __bfloat162float(hi));
    dst[(size_t)n * 256 + k] = hi;
    dst[(size_t)n * 256 + 128 + k] = lo;
}

// ---------------- activation hi/lo split (optional exact GELU) ----------------
template <bool GELU>
__global__ void __launch_bounds__(256) k_split(const float* __restrict__ src,
                                               __nv_bfloat16* __restrict__ dst, int M) {
    int idx = blockIdx.x * blockDim.x + threadIdx.x;
    if (idx >= M * 32) return;
    int row = idx >> 5, c4 = idx & 31;
    float4 v = *(const float4*)&src[(size_t)row * 128 + c4 * 4];
    if (GELU) {
        v.x *= normcdff(v.x); v.y *= normcdff(v.y);
        v.z *= normcdff(v.z); v.w *= normcdff(v.w);
    }
    __nv_bfloat16 hx = __float2bfloat16_rn(v.x);
    __nv_bfloat16 hy = __float2bfloat16_rn(v.y);
    __nv_bfloat16 hz = __float2bfloat16_rn(v.z);
    __nv_bfloat16 hw = __float2bfloat16_rn(v.w);
    __nv_bfloat16 lx = __float2bfloat16_rn(v.x - __bfloat162float(hx));
    __nv_bfloat16 ly = __float2bfloat16_rn(v.y - __bfloat162float(hy));
    __nv_bfloat16 lz = __float2bfloat16_rn(v.z - __bfloat162float(hz));
    __nv_bfloat16 lw = __float2bfloat16_rn(v.w - __bfloat162float(hw));
    __nv_bfloat162* dh = (__nv_bfloat162*)(dst + (size_t)row * 256 + c4 * 4);
    dh[0] = __halves2bfloat162(hx, hy);
    dh[1] = __halves2bfloat162(hz, hw);
    __nv_bfloat162* dl = (__nv_bfloat162*)(dst + (size_t)row * 256 + 128 + c4 * 4);
    dl[0] = __halves2bfloat162(lx, ly);
    dl[1] = __halves2bfloat162(lz, lw);
}

// ---------------- HMMA (mma.sync) bf16-split GEMM ----------------------------
// C[M x Ncols] = Afp32 @ W via Ah*Wh + Ah*Wl + Al*Wh, warp-level m16n8k16 MMA.
// CTA tile 128x128, K=128 resident. 8 warps: 4(m) x 2(n); warp tile 32x64.
// smem: 4 tiles (Ah, Al, Bh, Bl), each 128 rows x 128 cols bf16, row stride 136.
#define LDT 136
#define TILE_B (128 * LDT * 2)

__device__ __forceinline__ void ldsm_x4(uint32_t& r0, uint32_t& r1, uint32_t& r2,
                                        uint32_t& r3, uint32_t addr) {
    asm volatile("ldmatrix.sync.aligned.m8n8.x4.shared.b16 {%0,%1,%2,%3}, [%4];"
                 : "=r"(r0), "=r"(r1), "=r"(r2), "=r"(r3) : "r"(addr));
}

__device__ __forceinline__ void mma16816(float* d, uint32_t a0, uint32_t a1,
                                         uint32_t a2, uint32_t a3,
                                         uint32_t b0, uint32_t b1) {
    asm volatile(
        "mma.sync.aligned.m16n8k16.row.col.f32.bf16.bf16.f32 "
        "{%0,%1,%2,%3}, {%4,%5,%6,%7}, {%8,%9}, {%0,%1,%2,%3};"
        : "+f"(d[0]), "+f"(d[1]), "+f"(d[2]), "+f"(d[3])
        : "r"(a0), "r"(a1), "r"(a2), "r"(a3), "r"(b0), "r"(b1));
}

template <bool SKIP, bool WSPLIT>
__global__ void __launch_bounds__(256, 1) k_hmma(
    const __nv_bfloat16* __restrict__ Abf,
    const __nv_bfloat16* __restrict__ Bbf,
    const float* __restrict__ bias,
    float* __restrict__ C, int ldc, int M,
    const float* __restrict__ hold, int ldh,
    const float* __restrict__ skipp,
    __nv_bfloat16* __restrict__ splitout) {
    extern __shared__ __align__(16) char smem[];
    uint32_t smem_base;
    asm("{ .reg .u64 t; cvta.to.shared.u64 t, %1; cvt.u32.u64 %0, t; }"
        : "=r"(smem_base) : "l"(smem));
    const uint32_t A_H = 0, A_L = TILE_B, B_H = 2 * TILE_B, B_L = 3 * TILE_B;

    int tid = threadIdx.x, wid = tid >> 5, lane = tid & 31;
    int wm = wid & 3, wn = wid >> 2;
    int m0 = blockIdx.y * 128, n0 = blockIdx.x * 128;

    // ---- load tiles: A rows m0..m0+127, B rows n0..n0+127, hi|lo -> 4 tiles
    {
        const char* Ab = (const char*)Abf;
        const char* Bb = (const char*)Bbf;
#pragma unroll
        for (int it = 0; it < 16; it++) {
            int idx = it * 256 + tid;
            int r = idx >> 5, u = idx & 31;
            int gr = m0 + r;
            if (gr >= M) gr = M - 1;
            uint4 val = *(const uint4*)(Ab + (size_t)gr * 512 + u * 16);
            uint32_t dst = (u < 16 ? A_H : A_L) + (uint32_t)(r * LDT + (u & 15) * 8) * 2;
            *(uint4*)(smem + dst) = val;
        }
#pragma unroll
        for (int it = 0; it < 16; it++) {
            int idx = it * 256 + tid;
            int r = idx >> 5, u = idx & 31;
            uint4 val = *(const uint4*)(Bb + (size_t)(n0 + r) * 512 + u * 16);
            uint32_t dst = (u < 16 ? B_H : B_L) + (uint32_t)(r * LDT + (u & 15) * 8) * 2;
            *(uint4*)(smem + dst) = val;
        }
    }
    __syncthreads();

    // ---- per-lane ldmatrix address offsets (bytes, excluding k-step)
    uint32_t a_off[2], b_off[4];
#pragma unroll
    for (int mi = 0; mi < 2; mi++) {
        int arow = wm * 32 + mi * 16 + (lane & 7) + ((lane >> 3) & 1) * 8;
        int akc = (lane >> 4) * 8;
        a_off[mi] = (uint32_t)(arow * LDT + akc) * 2;
    }
#pragma unroll
    for (int p = 0; p < 4; p++) {
        int nrow = wn * 64 + p * 16 + (lane >> 4) * 8 + (lane & 7);
        int bkc = ((lane >> 3) & 1) * 8;
        b_off[p] = (uint32_t)(nrow * LDT + bkc) * 2;
    }

    float acc[2][8][4];
#pragma unroll
    for (int mi = 0; mi < 2; mi++)
#pragma unroll
        for (int ni = 0; ni < 8; ni++)
#pragma unroll
            for (int c = 0; c < 4; c++) acc[mi][ni][c] = 0.f;

    // ---- 3 split segments x 8 k16-steps
#pragma unroll
    for (int seg = 0; seg < 3; seg++) {
        uint32_t Aseg = smem_base + (seg == 2 ? A_L : A_H);
        uint32_t Bseg = smem_base + (seg == 1 ? B_L : B_H);
#pragma unroll
        for (int ks = 0; ks < 8; ks++) {
            uint32_t kb = (uint32_t)ks * 32;  // 16 bf16 = 32 bytes
            uint32_t af[2][4];
            ldsm_x4(af[0][0], af[0][1], af[0][2], af[0][3], Aseg + a_off[0] + kb);
            ldsm_x4(af[1][0], af[1][1], af[1][2], af[1][3], Aseg + a_off[1] + kb);
            uint32_t bf[8][2];
#pragma unroll
            for (int p = 0; p < 4; p++) {
                uint32_t r0, r1, r2, r3;
                ldsm_x4(r0, r1, r2, r3, Bseg + b_off[p] + kb);
                bf[p * 2][0] = r0; bf[p * 2][1] = r1;
                bf[p * 2 + 1][0] = r2; bf[p * 2 + 1][1] = r3;
            }
#pragma unroll
            for (int mi = 0; mi < 2; mi++)
#pragma unroll
                for (int ni = 0; ni < 8; ni++)
                    mma16816(acc[mi][ni], af[mi][0], af[mi][1], af[mi][2], af[mi][3],
                             bf[ni][0], bf[ni][1]);
        }
    }

    // ---- epilogue: bias (+ sigmoid-skip blend) (+ fused bf16 split)
    int groupID = lane >> 2, tg = lane & 3;
    float g = 0.f, og = 0.f;
    if (SKIP) {
        g = 1.f / (1.f + __expf(-skipp[0]));
        og = 1.f - g;
    }
#pragma unroll
    for (int mi = 0; mi < 2; mi++) {
#pragma unroll
        for (int hh = 0; hh < 2; hh++) {
            int row = m0 + wm * 32 + mi * 16 + groupID + hh * 8;
            if (row >= M) continue;
#pragma unroll
            for (int ni = 0; ni < 8; ni++) {
                int col = n0 + wn * 64 + ni * 8 + tg * 2;
                float v0 = acc[mi][ni][hh * 2]     + bias[col];
                float v1 = acc[mi][ni][hh * 2 + 1] + bias[col + 1];
                if (SKIP) {
                    float2 hv = *(const float2*)&hold[(size_t)row * ldh + col];
                    v0 = g * v0 + og * hv.x;
                    v1 = g * v1 + og * hv.y;
                }
                float2 o; o.x = v0; o.y = v1;
                *(float2*)&C[(size_t)row * ldc + col] = o;
                if (WSPLIT) {
                    __nv_bfloat16 h0 = __float2bfloat16_rn(v0);
                    __nv_bfloat16 h1 = __float2bfloat16_rn(v1);
                    __nv_bfloat16 l0 = __float2bfloat16_rn(v0 - __bfloat162float(h0));
                    __nv_bfloat16 l1 = __float2bfloat16_rn(v1 - __bfloat162float(h1));
                    *(__nv_bfloat162*)&splitout[(size_t)row * 256 + col] =
                        __halves2bfloat162(h0, h1);
                    *(__nv_bfloat162*)&splitout[(size_t)row * 256 + 128 + col] =
                        __halves2bfloat162(l0, l1);
                }
            }
        }
    }
}

// ---------------- edge phase: one warp per dst node, single pass --------------
__global__ void __launch_bounds__(256) k_edge(const float* __restrict__ prel) {
    int w = (blockIdx.x * blockDim.x + threadIdx.x) >> 5;
    int lane = threadIdx.x & 31;
    if (w >= NN) return;
    int r0 = g_rowstart[w], r1 = g_rowstart[w + 1];
    int h = lane >> 3;
    const float4 q4 = *(const float4*)&g_qkv[(size_t)w * 384 + lane * 4];
    const float scale = prel[h] * 0.17677669529663687f;  // p_rel / sqrt(32)
    float denom = 0.f;
    float4 acc = {0.f, 0.f, 0.f, 0.f};
    for (int j = r0; j < r1; j++) {
        int s = g_srcs[j];
        const float4 k4 = *(const float4*)&g_qkv[(size_t)s * 384 + 128 + lane * 4];
        const float4 v4 = *(const float4*)&g_qkv[(size_t)s * 384 + 256 + lane * 4];
        float p = q4.x * k4.x + q4.y * k4.y + q4.z * k4.z + q4.w * k4.w;
        p += __shfl_xor_sync(0xffffffffu, p, 1);
        p += __shfl_xor_sync(0xffffffffu, p, 2);
        p += __shfl_xor_sync(0xffffffffu, p, 4);
        float ev = __expf(p * scale);
        denom += ev;
        acc.x += ev * v4.x;
        acc.y += ev * v4.y;
        acc.z += ev * v4.z;
        acc.w += ev * v4.w;
    }
    float inv = (r1 > r0) ? 1.f / denom : 0.f;
    acc.x *= inv; acc.y *= inv; acc.z *= inv; acc.w *= inv;
    *(float4*)&g_agg[(size_t)w * CC + lane * 4] = acc;
}

// ---------------- final FC: out[N x 2] = h @ Wfc + bfc ------------------------
__global__ void __launch_bounds__(256) k_fc(const float* __restrict__ h,
                                            const float* __restrict__ Wfc,
                                            const float* __restrict__ bfc,
                                            float* __restrict__ out) {
    int w = (blockIdx.x * blockDim.x + threadIdx.x) >> 5;
    int lane = threadIdx.x & 31;
    if (w >= NN) return;
    float4 hv = *(const float4*)&h[(size_t)w * CC + lane * 4];
    float4 wa = *(const float4*)&Wfc[lane * 8];
    float4 wb = *(const float4*)&Wfc[lane * 8 + 4];
    float d0 = hv.x * wa.x + hv.y * wa.z + hv.z * wb.x + hv.w * wb.z;
    float d1 = hv.x * wa.y + hv.y * wa.w + hv.z * wb.y + hv.w * wb.w;
#pragma unroll
    for (int off = 16; off > 0; off >>= 1) {
        d0 += __shfl_xor_sync(0xffffffffu, d0, off);
        d1 += __shfl_xor_sync(0xffffffffu, d1, off);
    }
    if (lane == 0) {
        out[(size_t)w * 2]     = d0 + bfc[0];
        out[(size_t)w * 2 + 1] = d1 + bfc[1];
    }
}

// -----------------------------------------------------------------------------
extern "C" void kernel_launch(void* const* d_in, const int* in_sizes, int n_in,
                              void* d_out, int out_size) {
    const float* x     = (const float*)d_in[0];
    const void*  ei    = d_in[1];
    const float* Wk    = (const float*)d_in[2];
    const float* bk    = (const float*)d_in[3];
    const float* Wq    = (const float*)d_in[4];
    const float* bq    = (const float*)d_in[5];
    const float* Wv    = (const float*)d_in[6];
    const float* bv    = (const float*)d_in[7];
    const float* a_rel = (const float*)d_in[8];
    const float* m_rel = (const float*)d_in[9];
    const float* p_rel = (const float*)d_in[10];
    const float* Wa    = (const float*)d_in[11];
    const float* ba    = (const float*)d_in[12];
    const float* skip  = (const float*)d_in[13];
    const float* Wfc   = (const float*)d_in[14];
    const float* bfc   = (const float*)d_in[15];
    float* out = (float*)d_out;

    int E = in_sizes[1] / 2;
    if (E > EE) E = EE;

    float *p_h, *p_agg, *p_qkv, *p_W3, *p_b3;
    __nv_bfloat16 *p_abf, *p_w3bf, *p_wabf;
    cudaGetSymbolAddress((void**)&p_h, g_h);
    cudaGetSymbolAddress((void**)&p_agg, g_agg);
    cudaGetSymbolAddress((void**)&p_qkv, g_qkv);
    cudaGetSymbolAddress((void**)&p_W3, g_W3);
    cudaGetSymbolAddress((void**)&p_b3, g_b3);
    cudaGetSymbolAddress((void**)&p_abf, g_abf);
    cudaGetSymbolAddress((void**)&p_w3bf, g_w3bf);
    cudaGetSymbolAddress((void**)&p_wabf, g_wabf);

    const int SMEM_MMA = 4 * TILE_B;  // 139264 bytes
    cudaFuncSetAttribute(k_hmma<false, false>, cudaFuncAttributeMaxDynamicSharedMemorySize, SMEM_MMA);
    cudaFuncSetAttribute(k_hmma<true, true>,   cudaFuncAttributeMaxDynamicSharedMemorySize, SMEM_MMA);
    cudaFuncSetAttribute(k_hmma<true, false>,  cudaFuncAttributeMaxDynamicSharedMemorySize, SMEM_MMA);

    int eb = (E + 255) / 256;
    int nb1024 = (NN + 1023) / 1024;
    int mtiles = (NN + 127) / 128;          // 782
    int sgrid = (NN * 32 + 255) / 256;      // 12500

    k_detect<<<1, 1>>>(ei);
    k_zero<<<(NN + 255) / 256, 256>>>(NN);
    k_convert<<<eb, 256>>>(ei, E);
    k_scan1<<<nb1024, 1024>>>(NN);
    k_scan2<<<1, 128>>>(nb1024);
    k_scan3<<<(NN + 255) / 256, 256>>>(NN, E);
    k_scatter<<<eb, 256>>>(E);

    k_split<false><<<sgrid, 256>>>(x, p_abf, NN);

    for (int l = 0; l < LL; l++) {
        const float* A_prev = (l == 0) ? x : p_h;
        k_fold<<<(CC * 384 + 255) / 256, 256>>>(Wq, Wk, Wv, bq, bk, bv, a_rel, m_rel, l);
        k_wsplit<<<(384 * 128 + 255) / 256, 256>>>(p_W3, p_w3bf, 384);
        k_wsplit<<<(128 * 128 + 255) / 256, 256>>>(Wa + (size_t)l * CC * CC, p_wabf, 128);

        k_hmma<false, false><<<dim3(3, mtiles), 256, SMEM_MMA>>>(
            p_abf, p_w3bf, p_b3, p_qkv, 384, NN, nullptr, 0, nullptr, nullptr);

        k_edge<<<sgrid, 256>>>(p_rel + (size_t)l * HH);

        k_split<true><<<sgrid, 256>>>(p_agg, p_abf, NN);

        if (l == 0) {
            k_hmma<true, true><<<dim3(1, mtiles), 256, SMEM_MMA>>>(
                p_abf, p_wabf, ba + (size_t)l * CC, p_h, CC, NN, A_prev, CC, skip + l, p_abf);
        } else {
            k_hmma<true, false><<<dim3(1, mtiles), 256, SMEM_MMA>>>(
                p_abf, p_wabf, ba + (size_t)l * CC, p_h, CC, NN, A_prev, CC, skip + l, nullptr);
        }
    }
    k_fc<<<sgrid, 256>>>(p_h, Wfc, bfc, out);
}

// round 6
// speedup vs baseline: 1.8650x; 1.2545x over previous
#include <cuda_runtime.h>
#include <cuda_bf16.h>
#include <cuda_fp16.h>
#include <math.h>
#include <stdint.h>

#define NN 100000
#define CC 128
#define EE 1600000
#define HH 4
#define DD 32
#define LL 2

// ---------------- device scratch (allocation-free: static globals) ----------
__device__ int   g_is64;
__device__ int   g_src[EE];
__device__ int   g_dst[EE];
__device__ int   g_srcs[EE];
__device__ int   g_count[NN];
__device__ int   g_rowstart[NN + 2];
__device__ int   g_cursor[NN];
__device__ int   g_bsum[128];
__device__ int   g_bsum2[128];
__device__ float  g_q[(size_t)NN * 128];       // Q fp32
__device__ __half g_kv[(size_t)NN * 256];      // [n][0:128]=K' fp16  [128:256]=V' fp16
__device__ float g_agg[(size_t)NN * CC];
__device__ float g_h[(size_t)NN * CC];
__device__ float g_W3[CC * 384];               // folded fp32 [Wq | Wk@a_rel | Wv@m_rel]
__device__ float g_b3[384];
__device__ __nv_bfloat16 g_w3bf[384 * 256];    // W3^T split: [n][0:128]=hi [128:256]=lo
__device__ __nv_bfloat16 g_wabf[128 * 256];    // Wa^T split

// ---------------- edge-index dtype detection + conversion -------------------
__global__ void k_detect(const void* ei) {
    const long long* q = (const long long*)ei;
    int is64 = 1;
    for (int i = 0; i < 64; i++) {
        long long v = q[i];
        if (v < 0 || v >= NN) { is64 = 0; break; }
    }
    g_is64 = is64;
}

__global__ void k_zero(int n) {
    int i = blockIdx.x * blockDim.x + threadIdx.x;
    if (i < n) g_count[i] = 0;
}

__global__ void k_convert(const void* ei, int E) {
    int e = blockIdx.x * blockDim.x + threadIdx.x;
    if (e >= E) return;
    int s, d;
    if (g_is64) {
        const long long* p = (const long long*)ei;
        s = (int)p[e];
        d = (int)p[(size_t)E + e];
    } else {
        const int* p = (const int*)ei;
        s = p[e];
        d = p[(size_t)E + e];
    }
    g_src[e] = s;
    g_dst[e] = d;
    atomicAdd(&g_count[d], 1);
}

// ---------------- counting sort by dst ---------------------------------------
__global__ void k_scan1(int n) {
    __shared__ int sh[1024];
    int i = blockIdx.x * 1024 + threadIdx.x;
    int v = (i < n) ? g_count[i] : 0;
    sh[threadIdx.x] = v;
    __syncthreads();
    for (int off = 1; off < 1024; off <<= 1) {
        int t = (threadIdx.x >= off) ? sh[threadIdx.x - off] : 0;
        __syncthreads();
        sh[threadIdx.x] += t;
        __syncthreads();
    }
    if (i < n) g_rowstart[i] = sh[threadIdx.x] - v;
    if (threadIdx.x == 1023) g_bsum[blockIdx.x] = sh[1023];
}

__global__ void k_scan2(int nb) {
    __shared__ int sh[128];
    int v = (threadIdx.x < nb) ? g_bsum[threadIdx.x] : 0;
    sh[threadIdx.x] = v;
    __syncthreads();
    for (int off = 1; off < 128; off <<= 1) {
        int t = (threadIdx.x >= off) ? sh[threadIdx.x - off] : 0;
        __syncthreads();
        sh[threadIdx.x] += t;
        __syncthreads();
    }
    g_bsum2[threadIdx.x] = sh[threadIdx.x] - v;
}

__global__ void k_scan3(int n, int E) {
    int i = blockIdx.x * blockDim.x + threadIdx.x;
    if (i < n) {
        int r = g_rowstart[i] + g_bsum2[i >> 10];
        g_rowstart[i] = r;
        g_cursor[i] = r;
    }
    if (i == 0) g_rowstart[n] = E;
}

__global__ void k_scatter(int E) {
    int e = blockIdx.x * blockDim.x + threadIdx.x;
    if (e >= E) return;
    int d = g_dst[e];
    int pos = atomicAdd(&g_cursor[d], 1);
    g_srcs[pos] = g_src[e];
}

// ---------------- fold relation transforms into fp32 weights ------------------
__global__ void k_fold(const float* __restrict__ Wq, const float* __restrict__ Wk,
                       const float* __restrict__ Wv, const float* __restrict__ bq,
                       const float* __restrict__ bk, const float* __restrict__ bv,
                       const float* __restrict__ a_rel, const float* __restrict__ m_rel,
                       int l) {
    int idx = blockIdx.x * blockDim.x + threadIdx.x;
    if (idx >= CC * 384) return;
    int c = idx / 384, j = idx % 384;
    float val;
    if (j < 128) {
        val = Wq[((size_t)l * CC + c) * CC + j];
    } else {
        int e = (j < 256) ? j - 128 : j - 256;
        int h = e >> 5, ee = e & 31;
        const float* Wx = (j < 256) ? Wk : Wv;
        const float* Rx = (j < 256) ? a_rel : m_rel;
        const float* wrow = Wx + ((size_t)l * CC + c) * CC + h * DD;
        const float* rr = Rx + ((size_t)(l * HH + h) * DD) * DD + ee;
        float s = 0.f;
#pragma unroll
        for (int d = 0; d < DD; d++) s += wrow[d] * rr[d * DD];
        val = s;
    }
    g_W3[c * 384 + j] = val;
    if (c == 0) {
        float bval;
        if (j < 128) {
            bval = bq[l * CC + j];
        } else {
            int e = (j < 256) ? j - 128 : j - 256;
            int h = e >> 5, ee = e & 31;
            const float* bx = (j < 256) ? bk : bv;
            const float* Rx = (j < 256) ? a_rel : m_rel;
            float s = 0.f;
#pragma unroll
            for (int d = 0; d < DD; d++)
                s += bx[l * CC + h * DD + d] * Rx[((size_t)(l * HH + h) * DD + d) * DD + ee];
            bval = s;
        }
        g_b3[j] = bval;
    }
}

// ---------------- transpose + hi/lo bf16 split of weights --------------------
__global__ void k_wsplit(const float* __restrict__ W, __nv_bfloat16* __restrict__ dst,
                         int Ncols) {
    int idx = blockIdx.x * blockDim.x + threadIdx.x;
    if (idx >= 128 * Ncols) return;
    int n = idx >> 7, k = idx & 127;
    float v = W[(size_t)k * Ncols + n];
    __nv_bfloat16 hi = __float2bfloat16_rn(v);
    __nv_bfloat16 lo = __float2bfloat16_rn(v - __bfloat162float(hi));
    dst[(size_t)n * 256 + k] = hi;
    dst[(size_t)n * 256 + 128 + k] = lo;
}

// ---------------- HMMA (mma.sync) bf16-split GEMM ----------------------------
// C[M x Ncols] = Afp32 @ W via Ah*Wh + Ah*Wl + Al*Wh, warp-level m16n8k16 MMA.
// fp32 A is loaded from gmem and split (+optional GELU) into smem tiles in-kernel.
// CTA tile 128x128, K=128 resident. 8 warps: 4(m) x 2(n); warp tile 32x64.
#define LDT 136
#define TILE_B (128 * LDT * 2)

__device__ __forceinline__ void ldsm_x4(uint32_t& r0, uint32_t& r1, uint32_t& r2,
                                        uint32_t& r3, uint32_t addr) {
    asm volatile("ldmatrix.sync.aligned.m8n8.x4.shared.b16 {%0,%1,%2,%3}, [%4];"
                 : "=r"(r0), "=r"(r1), "=r"(r2), "=r"(r3) : "r"(addr));
}

__device__ __forceinline__ void mma16816(float* d, uint32_t a0, uint32_t a1,
                                         uint32_t a2, uint32_t a3,
                                         uint32_t b0, uint32_t b1) {
    asm volatile(
        "mma.sync.aligned.m16n8k16.row.col.f32.bf16.bf16.f32 "
        "{%0,%1,%2,%3}, {%4,%5,%6,%7}, {%8,%9}, {%0,%1,%2,%3};"
        : "+f"(d[0]), "+f"(d[1]), "+f"(d[2]), "+f"(d[3])
        : "r"(a0), "r"(a1), "r"(a2), "r"(a3), "r"(b0), "r"(b1));
}

__device__ __forceinline__ uint32_t pack_bf2(float a, float b) {
    __nv_bfloat162 t = __halves2bfloat162(__float2bfloat16_rn(a), __float2bfloat16_rn(b));
    uint32_t r;
    memcpy(&r, &t, 4);
    return r;
}

template <bool GELU, bool SKIP, bool QKVOUT>
__global__ void __launch_bounds__(256, 1) k_hmma(
    const float* __restrict__ A,
    const __nv_bfloat16* __restrict__ Bbf,
    const float* __restrict__ bias,
    float* __restrict__ Cq,            // fp32 out (Q block when QKVOUT)
    __half* __restrict__ kvout,        // fp16 out (K/V blocks when QKVOUT)
    int M,
    const float* __restrict__ hold,
    const float* __restrict__ skipp) {
    extern __shared__ __align__(16) char smem[];
    uint32_t smem_base;
    asm("{ .reg .u64 t; cvta.to.shared.u64 t, %1; cvt.u32.u64 %0, t; }"
        : "=r"(smem_base) : "l"(smem));
    const uint32_t A_H = 0, A_L = TILE_B, B_H = 2 * TILE_B, B_L = 3 * TILE_B;

    int tid = threadIdx.x, wid = tid >> 5, lane = tid & 31;
    int wm = wid & 3, wn = wid >> 2;
    int m0 = blockIdx.y * 128, n0 = blockIdx.x * 128;

    // ---- load A fp32, apply optional GELU, split hi/lo into smem tiles
#pragma unroll
    for (int it = 0; it < 16; it++) {
        int idx = it * 256 + tid;
        int r = idx >> 5, u = idx & 31;       // row, float4-index (32 per row)
        int gr = m0 + r;
        if (gr >= M) gr = M - 1;
        float4 v = *(const float4*)&A[(size_t)gr * 128 + u * 4];
        if (GELU) {
            v.x *= normcdff(v.x); v.y *= normcdff(v.y);
            v.z *= normcdff(v.z); v.w *= normcdff(v.w);
        }
        uint32_t h01 = pack_bf2(v.x, v.y), h23 = pack_bf2(v.z, v.w);
        float rx = v.x - __bfloat162float(__float2bfloat16_rn(v.x));
        float ry = v.y - __bfloat162float(__float2bfloat16_rn(v.y));
        float rz = v.z - __bfloat162float(__float2bfloat16_rn(v.z));
        float rw = v.w - __bfloat162float(__float2bfloat16_rn(v.w));
        uint32_t l01 = pack_bf2(rx, ry), l23 = pack_bf2(rz, rw);
        uint32_t off = (uint32_t)(r * LDT + u * 4) * 2;
        *(uint2*)(smem + A_H + off) = make_uint2(h01, h23);
        *(uint2*)(smem + A_L + off) = make_uint2(l01, l23);
    }
    // ---- load B tile (pre-split bf16): rows n0..n0+127
    {
        const char* Bb = (const char*)Bbf;
#pragma unroll
        for (int it = 0; it < 16; it++) {
            int idx = it * 256 + tid;
            int r = idx >> 5, u = idx & 31;
            uint4 val = *(const uint4*)(Bb + (size_t)(n0 + r) * 512 + u * 16);
            uint32_t dst = (u < 16 ? B_H : B_L) + (uint32_t)(r * LDT + (u & 15) * 8) * 2;
            *(uint4*)(smem + dst) = val;
        }
    }
    __syncthreads();

    // ---- per-lane ldmatrix address offsets
    uint32_t a_off[2], b_off[4];
#pragma unroll
    for (int mi = 0; mi < 2; mi++) {
        int arow = wm * 32 + mi * 16 + (lane & 7) + ((lane >> 3) & 1) * 8;
        int akc = (lane >> 4) * 8;
        a_off[mi] = (uint32_t)(arow * LDT + akc) * 2;
    }
#pragma unroll
    for (int p = 0; p < 4; p++) {
        int nrow = wn * 64 + p * 16 + (lane >> 4) * 8 + (lane & 7);
        int bkc = ((lane >> 3) & 1) * 8;
        b_off[p] = (uint32_t)(nrow * LDT + bkc) * 2;
    }

    float acc[2][8][4];
#pragma unroll
    for (int mi = 0; mi < 2; mi++)
#pragma unroll
        for (int ni = 0; ni < 8; ni++)
#pragma unroll
            for (int c = 0; c < 4; c++) acc[mi][ni][c] = 0.f;

    // ---- 3 split segments x 8 k16-steps
#pragma unroll
    for (int seg = 0; seg < 3; seg++) {
        uint32_t Aseg = smem_base + (seg == 2 ? A_L : A_H);
        uint32_t Bseg = smem_base + (seg == 1 ? B_L : B_H);
#pragma unroll
        for (int ks = 0; ks < 8; ks++) {
            uint32_t kb = (uint32_t)ks * 32;
            uint32_t af[2][4];
            ldsm_x4(af[0][0], af[0][1], af[0][2], af[0][3], Aseg + a_off[0] + kb);
            ldsm_x4(af[1][0], af[1][1], af[1][2], af[1][3], Aseg + a_off[1] + kb);
            uint32_t bf[8][2];
#pragma unroll
            for (int p = 0; p < 4; p++) {
                uint32_t r0, r1, r2, r3;
                ldsm_x4(r0, r1, r2, r3, Bseg + b_off[p] + kb);
                bf[p * 2][0] = r0; bf[p * 2][1] = r1;
                bf[p * 2 + 1][0] = r2; bf[p * 2 + 1][1] = r3;
            }
#pragma unroll
            for (int mi = 0; mi < 2; mi++)
#pragma unroll
                for (int ni = 0; ni < 8; ni++)
                    mma16816(acc[mi][ni], af[mi][0], af[mi][1], af[mi][2], af[mi][3],
                             bf[ni][0], bf[ni][1]);
        }
    }

    // ---- epilogue
    int groupID = lane >> 2, tg = lane & 3;
    float g = 0.f, og = 0.f;
    if (SKIP) {
        g = 1.f / (1.f + __expf(-skipp[0]));
        og = 1.f - g;
    }
#pragma unroll
    for (int mi = 0; mi < 2; mi++) {
#pragma unroll
        for (int hh = 0; hh < 2; hh++) {
            int row = m0 + wm * 32 + mi * 16 + groupID + hh * 8;
            if (row >= M) continue;
#pragma unroll
            for (int ni = 0; ni < 8; ni++) {
                int col = n0 + wn * 64 + ni * 8 + tg * 2;
                float v0 = acc[mi][ni][hh * 2]     + bias[col];
                float v1 = acc[mi][ni][hh * 2 + 1] + bias[col + 1];
                if (QKVOUT) {
                    if (n0 == 0) {
                        float2 o; o.x = v0; o.y = v1;
                        *(float2*)&Cq[(size_t)row * 128 + col] = o;
                    } else {
                        __half2 hv2 = __floats2half2_rn(v0, v1);
                        uint32_t bits;
                        memcpy(&bits, &hv2, 4);
                        *(uint32_t*)&kvout[(size_t)row * 256 + (col - 128)] = bits;
                    }
                } else {
                    if (SKIP) {
                        float2 hv = *(const float2*)&hold[(size_t)row * 128 + col];
                        v0 = g * v0 + og * hv.x;
                        v1 = g * v1 + og * hv.y;
                    }
                    float2 o; o.x = v0; o.y = v1;
                    *(float2*)&Cq[(size_t)row * 128 + col] = o;
                }
            }
        }
    }
}

// ---------------- edge phase: one warp per dst node, single pass --------------
// Q fp32, K/V fp16 (halves gather traffic; KV set is L2-resident at 51MB).
__global__ void __launch_bounds__(256) k_edge(const float* __restrict__ prel) {
    int w = (blockIdx.x * blockDim.x + threadIdx.x) >> 5;
    int lane = threadIdx.x & 31;
    if (w >= NN) return;
    int r0 = g_rowstart[w], r1 = g_rowstart[w + 1];
    int h = lane >> 3;
    const float4 q4 = *(const float4*)&g_q[(size_t)w * 128 + lane * 4];
    const float scale = prel[h] * 0.17677669529663687f;  // p_rel / sqrt(32)
    float denom = 0.f;
    float4 acc = {0.f, 0.f, 0.f, 0.f};
#pragma unroll 2
    for (int j = r0; j < r1; j++) {
        int s = g_srcs[j];
        const __half2* kp = (const __half2*)&g_kv[(size_t)s * 256 + lane * 4];
        const __half2* vp = (const __half2*)&g_kv[(size_t)s * 256 + 128 + lane * 4];
        __half2 k0 = kp[0], k1 = kp[1];
        __half2 v0 = vp[0], v1 = vp[1];
        float2 kf0 = __half22float2(k0), kf1 = __half22float2(k1);
        float p = q4.x * kf0.x + q4.y * kf0.y + q4.z * kf1.x + q4.w * kf1.y;
        p += __shfl_xor_sync(0xffffffffu, p, 1);
        p += __shfl_xor_sync(0xffffffffu, p, 2);
        p += __shfl_xor_sync(0xffffffffu, p, 4);
        float ev = __expf(p * scale);
        denom += ev;
        float2 vf0 = __half22float2(v0), vf1 = __half22float2(v1);
        acc.x += ev * vf0.x;
        acc.y += ev * vf0.y;
        acc.z += ev * vf1.x;
        acc.w += ev * vf1.y;
    }
    float inv = (r1 > r0) ? 1.f / denom : 0.f;
    acc.x *= inv; acc.y *= inv; acc.z *= inv; acc.w *= inv;
    *(float4*)&g_agg[(size_t)w * CC + lane * 4] = acc;
}

// ---------------- final FC: out[N x 2] = h @ Wfc + bfc ------------------------
__global__ void __launch_bounds__(256) k_fc(const float* __restrict__ h,
                                            const float* __restrict__ Wfc,
                                            const float* __restrict__ bfc,
                                            float* __restrict__ out) {
    int w = (blockIdx.x * blockDim.x + threadIdx.x) >> 5;
    int lane = threadIdx.x & 31;
    if (w >= NN) return;
    float4 hv = *(const float4*)&h[(size_t)w * CC + lane * 4];
    float4 wa = *(const float4*)&Wfc[lane * 8];
    float4 wb = *(const float4*)&Wfc[lane * 8 + 4];
    float d0 = hv.x * wa.x + hv.y * wa.z + hv.z * wb.x + hv.w * wb.z;
    float d1 = hv.x * wa.y + hv.y * wa.w + hv.z * wb.y + hv.w * wb.w;
#pragma unroll
    for (int off = 16; off > 0; off >>= 1) {
        d0 += __shfl_xor_sync(0xffffffffu, d0, off);
        d1 += __shfl_xor_sync(0xffffffffu, d1, off);
    }
    if (lane == 0) {
        out[(size_t)w * 2]     = d0 + bfc[0];
        out[(size_t)w * 2 + 1] = d1 + bfc[1];
    }
}

// -----------------------------------------------------------------------------
extern "C" void kernel_launch(void* const* d_in, const int* in_sizes, int n_in,
                              void* d_out, int out_size) {
    const float* x     = (const float*)d_in[0];
    const void*  ei    = d_in[1];
    const float* Wk    = (const float*)d_in[2];
    const float* bk    = (const float*)d_in[3];
    const float* Wq    = (const float*)d_in[4];
    const float* bq    = (const float*)d_in[5];
    const float* Wv    = (const float*)d_in[6];
    const float* bv    = (const float*)d_in[7];
    const float* a_rel = (const float*)d_in[8];
    const float* m_rel = (const float*)d_in[9];
    const float* p_rel = (const float*)d_in[10];
    const float* Wa    = (const float*)d_in[11];
    const float* ba    = (const float*)d_in[12];
    const float* skip  = (const float*)d_in[13];
    const float* Wfc   = (const float*)d_in[14];
    const float* bfc   = (const float*)d_in[15];
    float* out = (float*)d_out;

    int E = in_sizes[1] / 2;
    if (E > EE) E = EE;

    float *p_h, *p_agg, *p_q, *p_W3, *p_b3;
    __half* p_kv;
    __nv_bfloat16 *p_w3bf, *p_wabf;
    cudaGetSymbolAddress((void**)&p_h, g_h);
    cudaGetSymbolAddress((void**)&p_agg, g_agg);
    cudaGetSymbolAddress((void**)&p_q, g_q);
    cudaGetSymbolAddress((void**)&p_kv, g_kv);
    cudaGetSymbolAddress((void**)&p_W3, g_W3);
    cudaGetSymbolAddress((void**)&p_b3, g_b3);
    cudaGetSymbolAddress((void**)&p_w3bf, g_w3bf);
    cudaGetSymbolAddress((void**)&p_wabf, g_wabf);

    const int SMEM_MMA = 4 * TILE_B;  // 139264 bytes
    cudaFuncSetAttribute(k_hmma<false, false, true>,
                         cudaFuncAttributeMaxDynamicSharedMemorySize, SMEM_MMA);
    cudaFuncSetAttribute(k_hmma<true, true, false>,
                         cudaFuncAttributeMaxDynamicSharedMemorySize, SMEM_MMA);

    int eb = (E + 255) / 256;
    int nb1024 = (NN + 1023) / 1024;
    int mtiles = (NN + 127) / 128;          // 782
    int sgrid = (NN * 32 + 255) / 256;      // 12500

    k_detect<<<1, 1>>>(ei);
    k_zero<<<(NN + 255) / 256, 256>>>(NN);
    k_convert<<<eb, 256>>>(ei, E);
    k_scan1<<<nb1024, 1024>>>(NN);
    k_scan2<<<1, 128>>>(nb1024);
    k_scan3<<<(NN + 255) / 256, 256>>>(NN, E);
    k_scatter<<<eb, 256>>>(E);

    for (int l = 0; l < LL; l++) {
        const float* A_prev = (l == 0) ? x : p_h;
        k_fold<<<(CC * 384 + 255) / 256, 256>>>(Wq, Wk, Wv, bq, bk, bv, a_rel, m_rel, l);
        k_wsplit<<<(384 * 128 + 255) / 256, 256>>>(p_W3, p_w3bf, 384);
        k_wsplit<<<(128 * 128 + 255) / 256, 256>>>(Wa + (size_t)l * CC * CC, p_wabf, 128);

        k_hmma<false, false, true><<<dim3(3, mtiles), 256, SMEM_MMA>>>(
            A_prev, p_w3bf, p_b3, p_q, p_kv, NN, nullptr, nullptr);

        k_edge<<<sgrid, 256>>>(p_rel + (size_t)l * HH);

        k_hmma<true, true, false><<<dim3(1, mtiles), 256, SMEM_MMA>>>(
            p_agg, p_wabf, ba + (size_t)l * CC, p_h, nullptr, NN, A_prev, skip + l);
    }
    k_fc<<<sgrid, 256>>>(p_h, Wfc, bfc, out);
}

// round 7
// speedup vs baseline: 1.9250x; 1.0322x over previous
#include <cuda_runtime.h>
#include <cuda_bf16.h>
#include <cuda_fp16.h>
#include <math.h>
#include <stdint.h>

#define NN 100000
#define CC 128
#define EE 1600000
#define HH 4
#define DD 32
#define LL 2

// ---------------- device scratch (allocation-free: static globals) ----------
__device__ int   g_is64;
__device__ int   g_src[EE];
__device__ int   g_dst[EE];
__device__ int   g_srcs[EE];
__device__ int   g_count[NN];
__device__ int   g_rowstart[NN + 2];
__device__ int   g_cursor[NN];
__device__ int   g_bsum[128];
__device__ int   g_bsum2[128];
__device__ float  g_q[(size_t)NN * 128];       // Q fp32
__device__ __half g_kv[(size_t)NN * 256];      // [n][0:128]=K' fp16  [128:256]=V' fp16
__device__ float g_agg[(size_t)NN * CC];
__device__ float g_h[(size_t)NN * CC];
__device__ float g_W3[CC * 384];               // folded fp32 [Wq | Wk@a_rel | Wv@m_rel]
__device__ float g_b3[384];
__device__ __nv_bfloat16 g_w3bf[384 * 256];    // W3^T split: [n][0:128]=hi [128:256]=lo
__device__ __nv_bfloat16 g_wabf[128 * 256];    // Wa^T split

// ---------------- zero + edge-index dtype detection (fused) ------------------
__global__ void k_zero(const void* ei, int n) {
    int i = blockIdx.x * blockDim.x + threadIdx.x;
    if (i < n) g_count[i] = 0;
    if (blockIdx.x == 0 && threadIdx.x == 0) {
        const long long* q = (const long long*)ei;
        int is64 = 1;
        for (int k = 0; k < 64; k++) {
            long long v = q[k];
            if (v < 0 || v >= NN) { is64 = 0; break; }
        }
        g_is64 = is64;
    }
}

__global__ void k_convert(const void* ei, int E) {
    int e = blockIdx.x * blockDim.x + threadIdx.x;
    if (e >= E) return;
    int s, d;
    if (g_is64) {
        const long long* p = (const long long*)ei;
        s = (int)p[e];
        d = (int)p[(size_t)E + e];
    } else {
        const int* p = (const int*)ei;
        s = p[e];
        d = p[(size_t)E + e];
    }
    g_src[e] = s;
    g_dst[e] = d;
    atomicAdd(&g_count[d], 1);
}

// ---------------- counting sort by dst ---------------------------------------
__global__ void k_scan1(int n) {
    __shared__ int sh[1024];
    int i = blockIdx.x * 1024 + threadIdx.x;
    int v = (i < n) ? g_count[i] : 0;
    sh[threadIdx.x] = v;
    __syncthreads();
    for (int off = 1; off < 1024; off <<= 1) {
        int t = (threadIdx.x >= off) ? sh[threadIdx.x - off] : 0;
        __syncthreads();
        sh[threadIdx.x] += t;
        __syncthreads();
    }
    if (i < n) g_rowstart[i] = sh[threadIdx.x] - v;
    if (threadIdx.x == 1023) g_bsum[blockIdx.x] = sh[1023];
}

__global__ void k_scan2(int nb) {
    __shared__ int sh[128];
    int v = (threadIdx.x < nb) ? g_bsum[threadIdx.x] : 0;
    sh[threadIdx.x] = v;
    __syncthreads();
    for (int off = 1; off < 128; off <<= 1) {
        int t = (threadIdx.x >= off) ? sh[threadIdx.x - off] : 0;
        __syncthreads();
        sh[threadIdx.x] += t;
        __syncthreads();
    }
    g_bsum2[threadIdx.x] = sh[threadIdx.x] - v;
}

__global__ void k_scan3(int n, int E) {
    int i = blockIdx.x * blockDim.x + threadIdx.x;
    if (i < n) {
        int r = g_rowstart[i] + g_bsum2[i >> 10];
        g_rowstart[i] = r;
        g_cursor[i] = r;
    }
    if (i == 0) g_rowstart[n] = E;
}

__global__ void k_scatter(int E) {
    int e = blockIdx.x * blockDim.x + threadIdx.x;
    if (e >= E) return;
    int d = g_dst[e];
    int pos = atomicAdd(&g_cursor[d], 1);
    g_srcs[pos] = g_src[e];
}

// ---------------- fold relation transforms into fp32 weights ------------------
__global__ void k_fold(const float* __restrict__ Wq, const float* __restrict__ Wk,
                       const float* __restrict__ Wv, const float* __restrict__ bq,
                       const float* __restrict__ bk, const float* __restrict__ bv,
                       const float* __restrict__ a_rel, const float* __restrict__ m_rel,
                       int l) {
    int idx = blockIdx.x * blockDim.x + threadIdx.x;
    if (idx >= CC * 384) return;
    int c = idx / 384, j = idx % 384;
    float val;
    if (j < 128) {
        val = Wq[((size_t)l * CC + c) * CC + j];
    } else {
        int e = (j < 256) ? j - 128 : j - 256;
        int h = e >> 5, ee = e & 31;
        const float* Wx = (j < 256) ? Wk : Wv;
        const float* Rx = (j < 256) ? a_rel : m_rel;
        const float* wrow = Wx + ((size_t)l * CC + c) * CC + h * DD;
        const float* rr = Rx + ((size_t)(l * HH + h) * DD) * DD + ee;
        float s = 0.f;
#pragma unroll
        for (int d = 0; d < DD; d++) s += wrow[d] * rr[d * DD];
        val = s;
    }
    g_W3[c * 384 + j] = val;
    if (c == 0) {
        float bval;
        if (j < 128) {
            bval = bq[l * CC + j];
        } else {
            int e = (j < 256) ? j - 128 : j - 256;
            int h = e >> 5, ee = e & 31;
            const float* bx = (j < 256) ? bk : bv;
            const float* Rx = (j < 256) ? a_rel : m_rel;
            float s = 0.f;
#pragma unroll
            for (int d = 0; d < DD; d++)
                s += bx[l * CC + h * DD + d] * Rx[((size_t)(l * HH + h) * DD + d) * DD + ee];
            bval = s;
        }
        g_b3[j] = bval;
    }
}

// ---------------- transpose + hi/lo bf16 split of weights --------------------
__global__ void k_wsplit(const float* __restrict__ W, __nv_bfloat16* __restrict__ dst,
                         int Ncols) {
    int idx = blockIdx.x * blockDim.x + threadIdx.x;
    if (idx >= 128 * Ncols) return;
    int n = idx >> 7, k = idx & 127;
    float v = W[(size_t)k * Ncols + n];
    __nv_bfloat16 hi = __float2bfloat16_rn(v);
    __nv_bfloat16 lo = __float2bfloat16_rn(v - __bfloat162float(hi));
    dst[(size_t)n * 256 + k] = hi;
    dst[(size_t)n * 256 + 128 + k] = lo;
}

// ---------------- HMMA (mma.sync) bf16-split GEMM ----------------------------
// C[M x Ncols] = Afp32 @ W via Ah*Wh + Ah*Wl + Al*Wh, warp-level m16n8k16 MMA.
// fp32 A loaded once, split (+optional GELU) into smem; loops over NB B-tiles
// reusing the A tile (QKV: NB=3 -> A read once instead of 3x).
#define LDT 136
#define TILE_B (128 * LDT * 2)

__device__ __forceinline__ void ldsm_x4(uint32_t& r0, uint32_t& r1, uint32_t& r2,
                                        uint32_t& r3, uint32_t addr) {
    asm volatile("ldmatrix.sync.aligned.m8n8.x4.shared.b16 {%0,%1,%2,%3}, [%4];"
                 : "=r"(r0), "=r"(r1), "=r"(r2), "=r"(r3) : "r"(addr));
}

__device__ __forceinline__ void mma16816(float* d, uint32_t a0, uint32_t a1,
                                         uint32_t a2, uint32_t a3,
                                         uint32_t b0, uint32_t b1) {
    asm volatile(
        "mma.sync.aligned.m16n8k16.row.col.f32.bf16.bf16.f32 "
        "{%0,%1,%2,%3}, {%4,%5,%6,%7}, {%8,%9}, {%0,%1,%2,%3};"
        : "+f"(d[0]), "+f"(d[1]), "+f"(d[2]), "+f"(d[3])
        : "r"(a0), "r"(a1), "r"(a2), "r"(a3), "r"(b0), "r"(b1));
}

__device__ __forceinline__ uint32_t pack_bf2(float a, float b) {
    __nv_bfloat162 t = __halves2bfloat162(__float2bfloat16_rn(a), __float2bfloat16_rn(b));
    uint32_t r;
    memcpy(&r, &t, 4);
    return r;
}

template <bool GELU, bool SKIP, bool QKVOUT>
__global__ void __launch_bounds__(256, 1) k_hmma(
    const float* __restrict__ A,
    const __nv_bfloat16* __restrict__ Bbf,
    const float* __restrict__ bias,
    float* __restrict__ Cq,            // fp32 out (Q block when QKVOUT)
    __half* __restrict__ kvout,        // fp16 out (K/V blocks when QKVOUT)
    int M,
    const float* __restrict__ hold,
    const float* __restrict__ skipp) {
    extern __shared__ __align__(16) char smem[];
    uint32_t smem_base;
    asm("{ .reg .u64 t; cvta.to.shared.u64 t, %1; cvt.u32.u64 %0, t; }"
        : "=r"(smem_base) : "l"(smem));
    const uint32_t A_H = 0, A_L = TILE_B, B_H = 2 * TILE_B, B_L = 3 * TILE_B;

    int tid = threadIdx.x, wid = tid >> 5, lane = tid & 31;
    int wm = wid & 3, wn = wid >> 2;
    int m0 = blockIdx.y * 128;
    const int NB = QKVOUT ? 3 : 1;

    // ---- load A fp32, apply optional GELU, split hi/lo into smem tiles (once)
#pragma unroll
    for (int it = 0; it < 16; it++) {
        int idx = it * 256 + tid;
        int r = idx >> 5, u = idx & 31;       // row, float4-index (32 per row)
        int gr = m0 + r;
        if (gr >= M) gr = M - 1;
        float4 v = *(const float4*)&A[(size_t)gr * 128 + u * 4];
        if (GELU) {
            v.x *= normcdff(v.x); v.y *= normcdff(v.y);
            v.z *= normcdff(v.z); v.w *= normcdff(v.w);
        }
        uint32_t h01 = pack_bf2(v.x, v.y), h23 = pack_bf2(v.z, v.w);
        float rx = v.x - __bfloat162float(__float2bfloat16_rn(v.x));
        float ry = v.y - __bfloat162float(__float2bfloat16_rn(v.y));
        float rz = v.z - __bfloat162float(__float2bfloat16_rn(v.z));
        float rw = v.w - __bfloat162float(__float2bfloat16_rn(v.w));
        uint32_t l01 = pack_bf2(rx, ry), l23 = pack_bf2(rz, rw);
        uint32_t off = (uint32_t)(r * LDT + u * 4) * 2;
        *(uint2*)(smem + A_H + off) = make_uint2(h01, h23);
        *(uint2*)(smem + A_L + off) = make_uint2(l01, l23);
    }

    // ---- per-lane ldmatrix address offsets
    uint32_t a_off[2], b_off[4];
#pragma unroll
    for (int mi = 0; mi < 2; mi++) {
        int arow = wm * 32 + mi * 16 + (lane & 7) + ((lane >> 3) & 1) * 8;
        int akc = (lane >> 4) * 8;
        a_off[mi] = (uint32_t)(arow * LDT + akc) * 2;
    }
#pragma unroll
    for (int p = 0; p < 4; p++) {
        int nrow = wn * 64 + p * 16 + (lane >> 4) * 8 + (lane & 7);
        int bkc = ((lane >> 3) & 1) * 8;
        b_off[p] = (uint32_t)(nrow * LDT + bkc) * 2;
    }

    int groupID = lane >> 2, tg = lane & 3;
    float g = 0.f, og = 0.f;
    if (SKIP) {
        g = 1.f / (1.f + __expf(-skipp[0]));
        og = 1.f - g;
    }

    for (int bt = 0; bt < NB; bt++) {
        int n0 = bt * 128;
        __syncthreads();   // A stores visible / previous ldsm reads done
        // ---- load B tile (pre-split bf16): rows n0..n0+127
        {
            const char* Bb = (const char*)Bbf;
#pragma unroll
            for (int it = 0; it < 16; it++) {
                int idx = it * 256 + tid;
                int r = idx >> 5, u = idx & 31;
                uint4 val = *(const uint4*)(Bb + (size_t)(n0 + r) * 512 + u * 16);
                uint32_t dst = (u < 16 ? B_H : B_L) + (uint32_t)(r * LDT + (u & 15) * 8) * 2;
                *(uint4*)(smem + dst) = val;
            }
        }
        __syncthreads();

        float acc[2][8][4];
#pragma unroll
        for (int mi = 0; mi < 2; mi++)
#pragma unroll
            for (int ni = 0; ni < 8; ni++)
#pragma unroll
                for (int c = 0; c < 4; c++) acc[mi][ni][c] = 0.f;

        // ---- 3 split segments x 8 k16-steps
#pragma unroll
        for (int seg = 0; seg < 3; seg++) {
            uint32_t Aseg = smem_base + (seg == 2 ? A_L : A_H);
            uint32_t Bseg = smem_base + (seg == 1 ? B_L : B_H);
#pragma unroll
            for (int ks = 0; ks < 8; ks++) {
                uint32_t kb = (uint32_t)ks * 32;
                uint32_t af[2][4];
                ldsm_x4(af[0][0], af[0][1], af[0][2], af[0][3], Aseg + a_off[0] + kb);
                ldsm_x4(af[1][0], af[1][1], af[1][2], af[1][3], Aseg + a_off[1] + kb);
                uint32_t bf[8][2];
#pragma unroll
                for (int p = 0; p < 4; p++) {
                    uint32_t r0, r1, r2, r3;
                    ldsm_x4(r0, r1, r2, r3, Bseg + b_off[p] + kb);
                    bf[p * 2][0] = r0; bf[p * 2][1] = r1;
                    bf[p * 2 + 1][0] = r2; bf[p * 2 + 1][1] = r3;
                }
#pragma unroll
                for (int mi = 0; mi < 2; mi++)
#pragma unroll
                    for (int ni = 0; ni < 8; ni++)
                        mma16816(acc[mi][ni], af[mi][0], af[mi][1], af[mi][2], af[mi][3],
                                 bf[ni][0], bf[ni][1]);
            }
        }

        // ---- epilogue (registers + gmem only; no smem reads)
#pragma unroll
        for (int mi = 0; mi < 2; mi++) {
#pragma unroll
            for (int hh = 0; hh < 2; hh++) {
                int row = m0 + wm * 32 + mi * 16 + groupID + hh * 8;
                if (row >= M) continue;
#pragma unroll
                for (int ni = 0; ni < 8; ni++) {
                    int col = n0 + wn * 64 + ni * 8 + tg * 2;
                    float v0 = acc[mi][ni][hh * 2]     + bias[col];
                    float v1 = acc[mi][ni][hh * 2 + 1] + bias[col + 1];
                    if (QKVOUT) {
                        if (bt == 0) {
                            float2 o; o.x = v0; o.y = v1;
                            *(float2*)&Cq[(size_t)row * 128 + col] = o;
                        } else {
                            __half2 hv2 = __floats2half2_rn(v0, v1);
                            uint32_t bits;
                            memcpy(&bits, &hv2, 4);
                            *(uint32_t*)&kvout[(size_t)row * 256 + (col - 128)] = bits;
                        }
                    } else {
                        if (SKIP) {
                            float2 hv = *(const float2*)&hold[(size_t)row * 128 + col];
                            v0 = g * v0 + og * hv.x;
                            v1 = g * v1 + og * hv.y;
                        }
                        float2 o; o.x = v0; o.y = v1;
                        *(float2*)&Cq[(size_t)row * 128 + col] = o;
                    }
                }
            }
        }
    }
}

// ---------------- edge phase: one warp per dst node, 4-edge pipelined ---------
// Q fp32, K/V fp16 (L2-resident at 51MB). Batch 4 edges: 8 loads in flight.
__global__ void __launch_bounds__(256) k_edge(const float* __restrict__ prel) {
    int w = (blockIdx.x * blockDim.x + threadIdx.x) >> 5;
    int lane = threadIdx.x & 31;
    if (w >= NN) return;
    int r0 = g_rowstart[w], r1 = g_rowstart[w + 1];
    int h = lane >> 3;
    const float4 q4 = *(const float4*)&g_q[(size_t)w * 128 + lane * 4];
    const float scale = prel[h] * 0.17677669529663687f;  // p_rel / sqrt(32)
    float denom = 0.f;
    float4 acc = {0.f, 0.f, 0.f, 0.f};

    int j = r0;
    for (; j + 4 <= r1; j += 4) {
        int s[4];
#pragma unroll
        for (int u = 0; u < 4; u++) s[u] = g_srcs[j + u];
        uint2 kb[4], vb[4];
#pragma unroll
        for (int u = 0; u < 4; u++) {
            kb[u] = *(const uint2*)&g_kv[(size_t)s[u] * 256 + lane * 4];
            vb[u] = *(const uint2*)&g_kv[(size_t)s[u] * 256 + 128 + lane * 4];
        }
        float ev[4];
#pragma unroll
        for (int u = 0; u < 4; u++) {
            __half2 k0, k1;
            memcpy(&k0, &kb[u].x, 4); memcpy(&k1, &kb[u].y, 4);
            float2 kf0 = __half22float2(k0), kf1 = __half22float2(k1);
            float p = q4.x * kf0.x + q4.y * kf0.y + q4.z * kf1.x + q4.w * kf1.y;
            p += __shfl_xor_sync(0xffffffffu, p, 1);
            p += __shfl_xor_sync(0xffffffffu, p, 2);
            p += __shfl_xor_sync(0xffffffffu, p, 4);
            ev[u] = __expf(p * scale);
        }
#pragma unroll
        for (int u = 0; u < 4; u++) {
            __half2 v0, v1;
            memcpy(&v0, &vb[u].x, 4); memcpy(&v1, &vb[u].y, 4);
            float2 vf0 = __half22float2(v0), vf1 = __half22float2(v1);
            denom += ev[u];
            acc.x += ev[u] * vf0.x;
            acc.y += ev[u] * vf0.y;
            acc.z += ev[u] * vf1.x;
            acc.w += ev[u] * vf1.y;
        }
    }
    for (; j < r1; j++) {
        int s = g_srcs[j];
        uint2 kbits = *(const uint2*)&g_kv[(size_t)s * 256 + lane * 4];
        uint2 vbits = *(const uint2*)&g_kv[(size_t)s * 256 + 128 + lane * 4];
        __half2 k0, k1, v0, v1;
        memcpy(&k0, &kbits.x, 4); memcpy(&k1, &kbits.y, 4);
        memcpy(&v0, &vbits.x, 4); memcpy(&v1, &vbits.y, 4);
        float2 kf0 = __half22float2(k0), kf1 = __half22float2(k1);
        float p = q4.x * kf0.x + q4.y * kf0.y + q4.z * kf1.x + q4.w * kf1.y;
        p += __shfl_xor_sync(0xffffffffu, p, 1);
        p += __shfl_xor_sync(0xffffffffu, p, 2);
        p += __shfl_xor_sync(0xffffffffu, p, 4);
        float ev = __expf(p * scale);
        denom += ev;
        float2 vf0 = __half22float2(v0), vf1 = __half22float2(v1);
        acc.x += ev * vf0.x;
        acc.y += ev * vf0.y;
        acc.z += ev * vf1.x;
        acc.w += ev * vf1.y;
    }
    float inv = (r1 > r0) ? 1.f / denom : 0.f;
    acc.x *= inv; acc.y *= inv; acc.z *= inv; acc.w *= inv;
    *(float4*)&g_agg[(size_t)w * CC + lane * 4] = acc;
}

// ---------------- final FC: out[N x 2] = h @ Wfc + bfc ------------------------
__global__ void __launch_bounds__(256) k_fc(const float* __restrict__ h,
                                            const float* __restrict__ Wfc,
                                            const float* __restrict__ bfc,
                                            float* __restrict__ out) {
    int w = (blockIdx.x * blockDim.x + threadIdx.x) >> 5;
    int lane = threadIdx.x & 31;
    if (w >= NN) return;
    float4 hv = *(const float4*)&h[(size_t)w * CC + lane * 4];
    float4 wa = *(const float4*)&Wfc[lane * 8];
    float4 wb = *(const float4*)&Wfc[lane * 8 + 4];
    float d0 = hv.x * wa.x + hv.y * wa.z + hv.z * wb.x + hv.w * wb.z;
    float d1 = hv.x * wa.y + hv.y * wa.w + hv.z * wb.y + hv.w * wb.w;
#pragma unroll
    for (int off = 16; off > 0; off >>= 1) {
        d0 += __shfl_xor_sync(0xffffffffu, d0, off);
        d1 += __shfl_xor_sync(0xffffffffu, d1, off);
    }
    if (lane == 0) {
        out[(size_t)w * 2]     = d0 + bfc[0];
        out[(size_t)w * 2 + 1] = d1 + bfc[1];
    }
}

// -----------------------------------------------------------------------------
extern "C" void kernel_launch(void* const* d_in, const int* in_sizes, int n_in,
                              void* d_out, int out_size) {
    const float* x     = (const float*)d_in[0];
    const void*  ei    = d_in[1];
    const float* Wk    = (const float*)d_in[2];
    const float* bk    = (const float*)d_in[3];
    const float* Wq    = (const float*)d_in[4];
    const float* bq    = (const float*)d_in[5];
    const float* Wv    = (const float*)d_in[6];
    const float* bv    = (const float*)d_in[7];
    const float* a_rel = (const float*)d_in[8];
    const float* m_rel = (const float*)d_in[9];
    const float* p_rel = (const float*)d_in[10];
    const float* Wa    = (const float*)d_in[11];
    const float* ba    = (const float*)d_in[12];
    const float* skip  = (const float*)d_in[13];
    const float* Wfc   = (const float*)d_in[14];
    const float* bfc   = (const float*)d_in[15];
    float* out = (float*)d_out;

    int E = in_sizes[1] / 2;
    if (E > EE) E = EE;

    float *p_h, *p_agg, *p_q, *p_W3, *p_b3;
    __half* p_kv;
    __nv_bfloat16 *p_w3bf, *p_wabf;
    cudaGetSymbolAddress((void**)&p_h, g_h);
    cudaGetSymbolAddress((void**)&p_agg, g_agg);
    cudaGetSymbolAddress((void**)&p_q, g_q);
    cudaGetSymbolAddress((void**)&p_kv, g_kv);
    cudaGetSymbolAddress((void**)&p_W3, g_W3);
    cudaGetSymbolAddress((void**)&p_b3, g_b3);
    cudaGetSymbolAddress((void**)&p_w3bf, g_w3bf);
    cudaGetSymbolAddress((void**)&p_wabf, g_wabf);

    const int SMEM_MMA = 4 * TILE_B;  // 139264 bytes
    cudaFuncSetAttribute(k_hmma<false, false, true>,
                         cudaFuncAttributeMaxDynamicSharedMemorySize, SMEM_MMA);
    cudaFuncSetAttribute(k_hmma<true, true, false>,
                         cudaFuncAttributeMaxDynamicSharedMemorySize, SMEM_MMA);

    int eb = (E + 255) / 256;
    int nb1024 = (NN + 1023) / 1024;
    int mtiles = (NN + 127) / 128;          // 782
    int sgrid = (NN * 32 + 255) / 256;      // 12500

    k_zero<<<(NN + 255) / 256, 256>>>(ei, NN);
    k_convert<<<eb, 256>>>(ei, E);
    k_scan1<<<nb1024, 1024>>>(NN);
    k_scan2<<<1, 128>>>(nb1024);
    k_scan3<<<(NN + 255) / 256, 256>>>(NN, E);
    k_scatter<<<eb, 256>>>(E);

    for (int l = 0; l < LL; l++) {
        const float* A_prev = (l == 0) ? x : p_h;
        k_fold<<<(CC * 384 + 255) / 256, 256>>>(Wq, Wk, Wv, bq, bk, bv, a_rel, m_rel, l);
        k_wsplit<<<(384 * 128 + 255) / 256, 256>>>(p_W3, p_w3bf, 384);
        k_wsplit<<<(128 * 128 + 255) / 256, 256>>>(Wa + (size_t)l * CC * CC, p_wabf, 128);

        k_hmma<false, false, true><<<dim3(1, mtiles), 256, SMEM_MMA>>>(
            A_prev, p_w3bf, p_b3, p_q, p_kv, NN, nullptr, nullptr);

        k_edge<<<sgrid, 256>>>(p_rel + (size_t)l * HH);

        k_hmma<true, true, false><<<dim3(1, mtiles), 256, SMEM_MMA>>>(
            p_agg, p_wabf, ba + (size_t)l * CC, p_h, nullptr, NN, A_prev, skip + l);
    }
    k_fc<<<sgrid, 256>>>(p_h, Wfc, bfc, out);
}

// round 8
// speedup vs baseline: 1.9474x; 1.0116x over previous
#include <cuda_runtime.h>
#include <cuda_bf16.h>
#include <cuda_fp16.h>
#include <math.h>
#include <stdint.h>

#define NN 100000
#define CC 128
#define EE 1600000
#define HH 4
#define DD 32
#define LL 2

// ---------------- device scratch (allocation-free: static globals) ----------
__device__ int   g_is64;
__device__ int   g_src[EE];
__device__ int   g_dst[EE];
__device__ int   g_srcs[EE];
__device__ int   g_count[NN];
__device__ int   g_rowstart[NN + 2];
__device__ int   g_cursor[NN];
__device__ int   g_bsum[128];
__device__ int   g_bsum2[128];
__device__ __half g_qh[(size_t)NN * 128];      // Q fp16
__device__ __half g_kv[(size_t)NN * 256];      // [n][0:128]=K' fp16  [128:256]=V' fp16
__device__ float g_agg[(size_t)NN * CC];
__device__ float g_h[(size_t)NN * CC];
__device__ float g_b3[384];
__device__ __nv_bfloat16 g_w3bf[384 * 256];    // W3^T split: [n][0:128]=hi [128:256]=lo
__device__ __nv_bfloat16 g_wabf[128 * 256];    // Wa^T split

// ---------------- zero + edge-index dtype detection (fused) ------------------
__global__ void k_zero(const void* ei, int n) {
    int i = blockIdx.x * blockDim.x + threadIdx.x;
    if (i < n) g_count[i] = 0;
    if (blockIdx.x == 0 && threadIdx.x == 0) {
        const long long* q = (const long long*)ei;
        int is64 = 1;
        for (int k = 0; k < 64; k++) {
            long long v = q[k];
            if (v < 0 || v >= NN) { is64 = 0; break; }
        }
        g_is64 = is64;
    }
}

__global__ void k_convert(const void* ei, int E) {
    int e = blockIdx.x * blockDim.x + threadIdx.x;
    if (e >= E) return;
    int s, d;
    if (g_is64) {
        const long long* p = (const long long*)ei;
        s = (int)p[e];
        d = (int)p[(size_t)E + e];
    } else {
        const int* p = (const int*)ei;
        s = p[e];
        d = p[(size_t)E + e];
    }
    g_src[e] = s;
    g_dst[e] = d;
    atomicAdd(&g_count[d], 1);
}

// ---------------- counting sort by dst ---------------------------------------
__global__ void k_scan1(int n) {
    __shared__ int sh[1024];
    int i = blockIdx.x * 1024 + threadIdx.x;
    int v = (i < n) ? g_count[i] : 0;
    sh[threadIdx.x] = v;
    __syncthreads();
    for (int off = 1; off < 1024; off <<= 1) {
        int t = (threadIdx.x >= off) ? sh[threadIdx.x - off] : 0;
        __syncthreads();
        sh[threadIdx.x] += t;
        __syncthreads();
    }
    if (i < n) g_rowstart[i] = sh[threadIdx.x] - v;
    if (threadIdx.x == 1023) g_bsum[blockIdx.x] = sh[1023];
}

__global__ void k_scan2(int nb) {
    __shared__ int sh[128];
    int v = (threadIdx.x < nb) ? g_bsum[threadIdx.x] : 0;
    sh[threadIdx.x] = v;
    __syncthreads();
    for (int off = 1; off < 128; off <<= 1) {
        int t = (threadIdx.x >= off) ? sh[threadIdx.x - off] : 0;
        __syncthreads();
        sh[threadIdx.x] += t;
        __syncthreads();
    }
    g_bsum2[threadIdx.x] = sh[threadIdx.x] - v;
}

__global__ void k_scan3(int n, int E) {
    int i = blockIdx.x * blockDim.x + threadIdx.x;
    if (i < n) {
        int r = g_rowstart[i] + g_bsum2[i >> 10];
        g_rowstart[i] = r;
        g_cursor[i] = r;
    }
    if (i == 0) g_rowstart[n] = E;
}

__global__ void k_scatter(int E) {
    int e = blockIdx.x * blockDim.x + threadIdx.x;
    if (e >= E) return;
    int d = g_dst[e];
    int pos = atomicAdd(&g_cursor[d], 1);
    g_srcs[pos] = g_src[e];
}

// ---------------- fold relation transforms -> split transposed bf16 ----------
// Directly emits g_w3bf[j][0:128]=hi, [128:256]=lo of W3[c][j], plus g_b3.
__global__ void k_fold(const float* __restrict__ Wq, const float* __restrict__ Wk,
                       const float* __restrict__ Wv, const float* __restrict__ bq,
                       const float* __restrict__ bk, const float* __restrict__ bv,
                       const float* __restrict__ a_rel, const float* __restrict__ m_rel,
                       int l) {
    int idx = blockIdx.x * blockDim.x + threadIdx.x;
    if (idx >= CC * 384) return;
    int c = idx / 384, j = idx % 384;
    float val;
    if (j < 128) {
        val = Wq[((size_t)l * CC + c) * CC + j];
    } else {
        int e = (j < 256) ? j - 128 : j - 256;
        int h = e >> 5, ee = e & 31;
        const float* Wx = (j < 256) ? Wk : Wv;
        const float* Rx = (j < 256) ? a_rel : m_rel;
        const float* wrow = Wx + ((size_t)l * CC + c) * CC + h * DD;
        const float* rr = Rx + ((size_t)(l * HH + h) * DD) * DD + ee;
        float s = 0.f;
#pragma unroll
        for (int d = 0; d < DD; d++) s += wrow[d] * rr[d * DD];
        val = s;
    }
    __nv_bfloat16 hi = __float2bfloat16_rn(val);
    __nv_bfloat16 lo = __float2bfloat16_rn(val - __bfloat162float(hi));
    g_w3bf[(size_t)j * 256 + c] = hi;
    g_w3bf[(size_t)j * 256 + 128 + c] = lo;
    if (c == 0) {
        float bval;
        if (j < 128) {
            bval = bq[l * CC + j];
        } else {
            int e = (j < 256) ? j - 128 : j - 256;
            int h = e >> 5, ee = e & 31;
            const float* bx = (j < 256) ? bk : bv;
            const float* Rx = (j < 256) ? a_rel : m_rel;
            float s = 0.f;
#pragma unroll
            for (int d = 0; d < DD; d++)
                s += bx[l * CC + h * DD + d] * Rx[((size_t)(l * HH + h) * DD + d) * DD + ee];
            bval = s;
        }
        g_b3[j] = bval;
    }
}

// ---------------- transpose + hi/lo bf16 split of Wa --------------------------
__global__ void k_wsplit(const float* __restrict__ W, __nv_bfloat16* __restrict__ dst,
                         int Ncols) {
    int idx = blockIdx.x * blockDim.x + threadIdx.x;
    if (idx >= 128 * Ncols) return;
    int n = idx >> 7, k = idx & 127;
    float v = W[(size_t)k * Ncols + n];
    __nv_bfloat16 hi = __float2bfloat16_rn(v);
    __nv_bfloat16 lo = __float2bfloat16_rn(v - __bfloat162float(hi));
    dst[(size_t)n * 256 + k] = hi;
    dst[(size_t)n * 256 + 128 + k] = lo;
}

// ---------------- HMMA (mma.sync) bf16-split GEMM ----------------------------
// C[M x *] = Afp32 @ W via Ah*Wh + Ah*Wl + Al*Wh, warp-level m16n8k16 MMA.
// CTA tile 128(M) x 64(N); A tile resident, loops over NB 64-col B subtiles.
// smem 104KB -> 2 CTAs/SM. 8 warps: 4(m) x 2(n); warp tile 32x32.
#define LDT 136
#define A_TILE (128 * LDT * 2)
#define B_TILE (64 * LDT * 2)
#define SM_AH 0
#define SM_AL A_TILE
#define SM_BH (2 * A_TILE)
#define SM_BL (2 * A_TILE + B_TILE)
#define SM_FC (2 * A_TILE + 2 * B_TILE)
#define SMEM_MMA (SM_FC + 2048)

__device__ __forceinline__ void ldsm_x4(uint32_t& r0, uint32_t& r1, uint32_t& r2,
                                        uint32_t& r3, uint32_t addr) {
    asm volatile("ldmatrix.sync.aligned.m8n8.x4.shared.b16 {%0,%1,%2,%3}, [%4];"
                 : "=r"(r0), "=r"(r1), "=r"(r2), "=r"(r3) : "r"(addr));
}

__device__ __forceinline__ void mma16816(float* d, uint32_t a0, uint32_t a1,
                                         uint32_t a2, uint32_t a3,
                                         uint32_t b0, uint32_t b1) {
    asm volatile(
        "mma.sync.aligned.m16n8k16.row.col.f32.bf16.bf16.f32 "
        "{%0,%1,%2,%3}, {%4,%5,%6,%7}, {%8,%9}, {%0,%1,%2,%3};"
        : "+f"(d[0]), "+f"(d[1]), "+f"(d[2]), "+f"(d[3])
        : "r"(a0), "r"(a1), "r"(a2), "r"(a3), "r"(b0), "r"(b1));
}

__device__ __forceinline__ uint32_t pack_bf2(float a, float b) {
    __nv_bfloat162 t = __halves2bfloat162(__float2bfloat16_rn(a), __float2bfloat16_rn(b));
    uint32_t r;
    memcpy(&r, &t, 4);
    return r;
}

template <bool GELU, bool SKIP, bool QKVOUT, bool FC>
__global__ void __launch_bounds__(256, 2) k_hmma(
    const float* __restrict__ A,
    const __nv_bfloat16* __restrict__ Bbf,
    const float* __restrict__ bias,
    float* __restrict__ Cq,            // fp32 out (non-QKV, non-FC)
    __half* __restrict__ qh,           // Q fp16 out (QKVOUT, bt<2)
    __half* __restrict__ kvout,        // K/V fp16 out (QKVOUT, bt>=2)
    int M,
    const float* __restrict__ hold,
    const float* __restrict__ skipp,
    const float* __restrict__ Wfc,
    const float* __restrict__ bfc,
    float* __restrict__ outp) {
    extern __shared__ __align__(16) char smem[];
    uint32_t smem_base;
    asm("{ .reg .u64 t; cvta.to.shared.u64 t, %1; cvt.u32.u64 %0, t; }"
        : "=r"(smem_base) : "l"(smem));

    int tid = threadIdx.x, wid = tid >> 5, lane = tid & 31;
    int wm = wid & 3, wn = wid >> 2;
    int m0 = blockIdx.x * 128;
    const int NB = QKVOUT ? 6 : 2;

    // ---- load A fp32, optional GELU, split hi/lo into smem (once)
#pragma unroll
    for (int it = 0; it < 16; it++) {
        int idx = it * 256 + tid;
        int r = idx >> 5, u = idx & 31;
        int gr = m0 + r;
        if (gr >= M) gr = M - 1;
        float4 v = *(const float4*)&A[(size_t)gr * 128 + u * 4];
        if (GELU) {
            v.x *= normcdff(v.x); v.y *= normcdff(v.y);
            v.z *= normcdff(v.z); v.w *= normcdff(v.w);
        }
        uint32_t h01 = pack_bf2(v.x, v.y), h23 = pack_bf2(v.z, v.w);
        float rx = v.x - __bfloat162float(__float2bfloat16_rn(v.x));
        float ry = v.y - __bfloat162float(__float2bfloat16_rn(v.y));
        float rz = v.z - __bfloat162float(__float2bfloat16_rn(v.z));
        float rw = v.w - __bfloat162float(__float2bfloat16_rn(v.w));
        uint32_t l01 = pack_bf2(rx, ry), l23 = pack_bf2(rz, rw);
        uint32_t off = (uint32_t)(r * LDT + u * 4) * 2;
        *(uint2*)(smem + SM_AH + off) = make_uint2(h01, h23);
        *(uint2*)(smem + SM_AL + off) = make_uint2(l01, l23);
    }

    // ---- per-lane ldmatrix offsets
    uint32_t a_off[2], b_off[2];
#pragma unroll
    for (int mi = 0; mi < 2; mi++) {
        int arow = wm * 32 + mi * 16 + (lane & 7) + ((lane >> 3) & 1) * 8;
        int akc = (lane >> 4) * 8;
        a_off[mi] = (uint32_t)(arow * LDT + akc) * 2;
    }
#pragma unroll
    for (int p = 0; p < 2; p++) {
        int nrow = wn * 32 + p * 16 + (lane >> 4) * 8 + (lane & 7);
        int bkc = ((lane >> 3) & 1) * 8;
        b_off[p] = (uint32_t)(nrow * LDT + bkc) * 2;
    }

    int groupID = lane >> 2, tg = lane & 3;
    float g = 0.f, og = 0.f;
    if (SKIP) {
        g = 1.f / (1.f + __expf(-skipp[0]));
        og = 1.f - g;
    }
    float fc0[2][2], fc1[2][2];
    if (FC) {
#pragma unroll
        for (int mi = 0; mi < 2; mi++)
#pragma unroll
            for (int hh = 0; hh < 2; hh++) { fc0[mi][hh] = 0.f; fc1[mi][hh] = 0.f; }
    }

    for (int bt = 0; bt < NB; bt++) {
        int n0 = bt * 64;
        __syncthreads();
        // ---- load B subtile (64 rows x 256 bf16 hi|lo)
        {
            const char* Bb = (const char*)Bbf;
#pragma unroll
            for (int it = 0; it < 8; it++) {
                int idx = it * 256 + tid;
                int r = idx >> 5, u = idx & 31;
                uint4 val = *(const uint4*)(Bb + (size_t)(n0 + r) * 512 + u * 16);
                uint32_t dst = (u < 16 ? SM_BH : SM_BL) + (uint32_t)(r * LDT + (u & 15) * 8) * 2;
                *(uint4*)(smem + dst) = val;
            }
        }
        __syncthreads();

        float acc[2][4][4];
#pragma unroll
        for (int mi = 0; mi < 2; mi++)
#pragma unroll
            for (int ni = 0; ni < 4; ni++)
#pragma unroll
                for (int c = 0; c < 4; c++) acc[mi][ni][c] = 0.f;

#pragma unroll
        for (int seg = 0; seg < 3; seg++) {
            uint32_t Aseg = smem_base + (seg == 2 ? SM_AL : SM_AH);
            uint32_t Bseg = smem_base + (seg == 1 ? SM_BL : SM_BH);
#pragma unroll
            for (int ks = 0; ks < 8; ks++) {
                uint32_t kb = (uint32_t)ks * 32;
                uint32_t af[2][4];
                ldsm_x4(af[0][0], af[0][1], af[0][2], af[0][3], Aseg + a_off[0] + kb);
                ldsm_x4(af[1][0], af[1][1], af[1][2], af[1][3], Aseg + a_off[1] + kb);
                uint32_t bf[4][2];
#pragma unroll
                for (int p = 0; p < 2; p++) {
                    uint32_t r0, r1, r2, r3;
                    ldsm_x4(r0, r1, r2, r3, Bseg + b_off[p] + kb);
                    bf[p * 2][0] = r0; bf[p * 2][1] = r1;
                    bf[p * 2 + 1][0] = r2; bf[p * 2 + 1][1] = r3;
                }
#pragma unroll
                for (int mi = 0; mi < 2; mi++)
#pragma unroll
                    for (int ni = 0; ni < 4; ni++)
                        mma16816(acc[mi][ni], af[mi][0], af[mi][1], af[mi][2], af[mi][3],
                                 bf[ni][0], bf[ni][1]);
            }
        }

        // ---- epilogue
#pragma unroll
        for (int mi = 0; mi < 2; mi++) {
#pragma unroll
            for (int hh = 0; hh < 2; hh++) {
                int row = m0 + wm * 32 + mi * 16 + groupID + hh * 8;
                bool rok = row < M;
#pragma unroll
                for (int ni = 0; ni < 4; ni++) {
                    int col = n0 + wn * 32 + ni * 8 + tg * 2;
                    float v0 = acc[mi][ni][hh * 2]     + bias[col];
                    float v1 = acc[mi][ni][hh * 2 + 1] + bias[col + 1];
                    if (QKVOUT) {
                        if (bt < 2) {
                            if (rok) {
                                __half2 hv2 = __floats2half2_rn(v0, v1);
                                uint32_t bits; memcpy(&bits, &hv2, 4);
                                *(uint32_t*)&qh[(size_t)row * 128 + col] = bits;
                            }
                        } else {
                            if (rok) {
                                __half2 hv2 = __floats2half2_rn(v0, v1);
                                uint32_t bits; memcpy(&bits, &hv2, 4);
                                *(uint32_t*)&kvout[(size_t)row * 256 + (col - 128)] = bits;
                            }
                        }
                    } else {
                        if (SKIP) {
                            float2 hv = *(const float2*)&hold[(size_t)row * 128 + col];
                            v0 = g * v0 + og * hv.x;
                            v1 = g * v1 + og * hv.y;
                        }
                        if (!FC) {
                            if (rok) {
                                float2 o; o.x = v0; o.y = v1;
                                *(float2*)&Cq[(size_t)row * 128 + col] = o;
                            }
                        } else {
                            fc0[mi][hh] += v0 * Wfc[col * 2]     + v1 * Wfc[col * 2 + 2];
                            fc1[mi][hh] += v0 * Wfc[col * 2 + 1] + v1 * Wfc[col * 2 + 3];
                        }
                    }
                }
            }
        }
    }

    if (FC) {
        float* fcbuf = (float*)(smem + SM_FC);   // [2 wn][128 row][2]
#pragma unroll
        for (int mi = 0; mi < 2; mi++) {
#pragma unroll
            for (int hh = 0; hh < 2; hh++) {
                float a0 = fc0[mi][hh], a1 = fc1[mi][hh];
                a0 += __shfl_xor_sync(0xffffffffu, a0, 1);
                a0 += __shfl_xor_sync(0xffffffffu, a0, 2);
                a1 += __shfl_xor_sync(0xffffffffu, a1, 1);
                a1 += __shfl_xor_sync(0xffffffffu, a1, 2);
                int rowl = wm * 32 + mi * 16 + groupID + hh * 8;
                if (tg == 0) {
                    fcbuf[(wn * 128 + rowl) * 2]     = a0;
                    fcbuf[(wn * 128 + rowl) * 2 + 1] = a1;
                }
            }
        }
        __syncthreads();
        if (tid < 128) {
            int gr = m0 + tid;
            if (gr < M) {
                float o0 = fcbuf[tid * 2]     + fcbuf[(128 + tid) * 2]     + bfc[0];
                float o1 = fcbuf[tid * 2 + 1] + fcbuf[(128 + tid) * 2 + 1] + bfc[1];
                outp[(size_t)gr * 2]     = o0;
                outp[(size_t)gr * 2 + 1] = o1;
            }
        }
    }
}

// ---------------- edge phase: one warp per dst node, 4-edge batched -----------
// Q fp16, K/V fp16 (L2-resident). Single pass fused softmax+aggregate.
__global__ void __launch_bounds__(256) k_edge(const float* __restrict__ prel) {
    int w = (blockIdx.x * blockDim.x + threadIdx.x) >> 5;
    int lane = threadIdx.x & 31;
    if (w >= NN) return;
    int r0 = g_rowstart[w], r1 = g_rowstart[w + 1];
    int h = lane >> 3;
    uint2 qb = *(const uint2*)&g_qh[(size_t)w * 128 + lane * 4];
    __half2 qh0, qh1;
    memcpy(&qh0, &qb.x, 4); memcpy(&qh1, &qb.y, 4);
    float2 qf0 = __half22float2(qh0), qf1 = __half22float2(qh1);
    const float4 q4 = {qf0.x, qf0.y, qf1.x, qf1.y};
    const float scale = prel[h] * 0.17677669529663687f;  // p_rel / sqrt(32)
    float denom = 0.f;
    float4 acc = {0.f, 0.f, 0.f, 0.f};

    int j = r0;
    for (; j + 4 <= r1; j += 4) {
        int s[4];
#pragma unroll
        for (int u = 0; u < 4; u++) s[u] = g_srcs[j + u];
        uint2 kb[4], vb[4];
#pragma unroll
        for (int u = 0; u < 4; u++) {
            kb[u] = *(const uint2*)&g_kv[(size_t)s[u] * 256 + lane * 4];
            vb[u] = *(const uint2*)&g_kv[(size_t)s[u] * 256 + 128 + lane * 4];
        }
        float ev[4];
#pragma unroll
        for (int u = 0; u < 4; u++) {
            __half2 k0, k1;
            memcpy(&k0, &kb[u].x, 4); memcpy(&k1, &kb[u].y, 4);
            float2 kf0 = __half22float2(k0), kf1 = __half22float2(k1);
            float p = q4.x * kf0.x + q4.y * kf0.y + q4.z * kf1.x + q4.w * kf1.y;
            p += __shfl_xor_sync(0xffffffffu, p, 1);
            p += __shfl_xor_sync(0xffffffffu, p, 2);
            p += __shfl_xor_sync(0xffffffffu, p, 4);
            ev[u] = __expf(p * scale);
        }
#pragma unroll
        for (int u = 0; u < 4; u++) {
            __half2 v0, v1;
            memcpy(&v0, &vb[u].x, 4); memcpy(&v1, &vb[u].y, 4);
            float2 vf0 = __half22float2(v0), vf1 = __half22float2(v1);
            denom += ev[u];
            acc.x += ev[u] * vf0.x;
            acc.y += ev[u] * vf0.y;
            acc.z += ev[u] * vf1.x;
            acc.w += ev[u] * vf1.y;
        }
    }
    for (; j < r1; j++) {
        int s = g_srcs[j];
        uint2 kbits = *(const uint2*)&g_kv[(size_t)s * 256 + lane * 4];
        uint2 vbits = *(const uint2*)&g_kv[(size_t)s * 256 + 128 + lane * 4];
        __half2 k0, k1, v0, v1;
        memcpy(&k0, &kbits.x, 4); memcpy(&k1, &kbits.y, 4);
        memcpy(&v0, &vbits.x, 4); memcpy(&v1, &vbits.y, 4);
        float2 kf0 = __half22float2(k0), kf1 = __half22float2(k1);
        float p = q4.x * kf0.x + q4.y * kf0.y + q4.z * kf1.x + q4.w * kf1.y;
        p += __shfl_xor_sync(0xffffffffu, p, 1);
        p += __shfl_xor_sync(0xffffffffu, p, 2);
        p += __shfl_xor_sync(0xffffffffu, p, 4);
        float ev = __expf(p * scale);
        denom += ev;
        float2 vf0 = __half22float2(v0), vf1 = __half22float2(v1);
        acc.x += ev * vf0.x;
        acc.y += ev * vf0.y;
        acc.z += ev * vf1.x;
        acc.w += ev * vf1.y;
    }
    float inv = (r1 > r0) ? 1.f / denom : 0.f;
    acc.x *= inv; acc.y *= inv; acc.z *= inv; acc.w *= inv;
    *(float4*)&g_agg[(size_t)w * CC + lane * 4] = acc;
}

// -----------------------------------------------------------------------------
extern "C" void kernel_launch(void* const* d_in, const int* in_sizes, int n_in,
                              void* d_out, int out_size) {
    const float* x     = (const float*)d_in[0];
    const void*  ei    = d_in[1];
    const float* Wk    = (const float*)d_in[2];
    const float* bk    = (const float*)d_in[3];
    const float* Wq    = (const float*)d_in[4];
    const float* bq    = (const float*)d_in[5];
    const float* Wv    = (const float*)d_in[6];
    const float* bv    = (const float*)d_in[7];
    const float* a_rel = (const float*)d_in[8];
    const float* m_rel = (const float*)d_in[9];
    const float* p_rel = (const float*)d_in[10];
    const float* Wa    = (const float*)d_in[11];
    const float* ba    = (const float*)d_in[12];
    const float* skip  = (const float*)d_in[13];
    const float* Wfc   = (const float*)d_in[14];
    const float* bfc   = (const float*)d_in[15];
    float* out = (float*)d_out;

    int E = in_sizes[1] / 2;
    if (E > EE) E = EE;

    float *p_h, *p_agg, *p_b3;
    __half *p_qh, *p_kv;
    __nv_bfloat16 *p_w3bf, *p_wabf;
    cudaGetSymbolAddress((void**)&p_h, g_h);
    cudaGetSymbolAddress((void**)&p_agg, g_agg);
    cudaGetSymbolAddress((void**)&p_qh, g_qh);
    cudaGetSymbolAddress((void**)&p_kv, g_kv);
    cudaGetSymbolAddress((void**)&p_b3, g_b3);
    cudaGetSymbolAddress((void**)&p_w3bf, g_w3bf);
    cudaGetSymbolAddress((void**)&p_wabf, g_wabf);

    cudaFuncSetAttribute(k_hmma<false, false, true, false>,
                         cudaFuncAttributeMaxDynamicSharedMemorySize, SMEM_MMA);
    cudaFuncSetAttribute(k_hmma<true, true, false, false>,
                         cudaFuncAttributeMaxDynamicSharedMemorySize, SMEM_MMA);
    cudaFuncSetAttribute(k_hmma<true, true, false, true>,
                         cudaFuncAttributeMaxDynamicSharedMemorySize, SMEM_MMA);

    int eb = (E + 255) / 256;
    int nb1024 = (NN + 1023) / 1024;
    int mtiles = (NN + 127) / 128;          // 782
    int sgrid = (NN * 32 + 255) / 256;      // 12500

    k_zero<<<(NN + 255) / 256, 256>>>(ei, NN);
    k_convert<<<eb, 256>>>(ei, E);
    k_scan1<<<nb1024, 1024>>>(NN);
    k_scan2<<<1, 128>>>(nb1024);
    k_scan3<<<(NN + 255) / 256, 256>>>(NN, E);
    k_scatter<<<eb, 256>>>(E);

    for (int l = 0; l < LL; l++) {
        const float* A_prev = (l == 0) ? x : p_h;
        k_fold<<<(CC * 384 + 255) / 256, 256>>>(Wq, Wk, Wv, bq, bk, bv, a_rel, m_rel, l);
        k_wsplit<<<(128 * 128 + 255) / 256, 256>>>(Wa + (size_t)l * CC * CC, p_wabf, 128);

        k_hmma<false, false, true, false><<<mtiles, 256, SMEM_MMA>>>(
            A_prev, p_w3bf, p_b3, nullptr, p_qh, p_kv, NN,
            nullptr, nullptr, nullptr, nullptr, nullptr);

        k_edge<<<sgrid, 256>>>(p_rel + (size_t)l * HH);

        if (l == 0) {
            k_hmma<true, true, false, false><<<mtiles, 256, SMEM_MMA>>>(
                p_agg, p_wabf, ba + (size_t)l * CC, p_h, nullptr, nullptr, NN,
                A_prev, skip + l, nullptr, nullptr, nullptr);
        } else {
            k_hmma<true, true, false, true><<<mtiles, 256, SMEM_MMA>>>(
                p_agg, p_wabf, ba + (size_t)l * CC, nullptr, nullptr, nullptr, NN,
                A_prev, skip + l, Wfc, bfc, out);
        }
    }
}